// round 12
// baseline (speedup 1.0000x reference)
#include <cuda_runtime.h>
#include <math.h>
#include <stdint.h>

#define B_ 512
#define C_ 3
#define N_ 1024
#define D_ 2048
#define CD (C_*D_)
#define CN (C_*N_)
#define TAU 0.1f
#define LAM 0.1f
#define NLAYERS 30

// ---------------- scratch (static device globals) ----------------
__device__ float  g_gram[(size_t)C_ * D_ * D_];   // fp32 Gram temp
__device__ float2 g_m2[(size_t)C_ * D_ * D_];     // (hi,lo) of M2 = TAU*G - I
__device__ float  g_y[(size_t)B_ * C_ * D_];      // y2 = TAU * y
__device__ float  g_n0[(size_t)B_ * C_ * D_];     // z state fp32, ping
__device__ float  g_n1[(size_t)B_ * C_ * D_];     // pong
__device__ float2 g_s0[(size_t)B_ * C_ * D_];     // momentum (hi,lo), ping
__device__ float2 g_s1[(size_t)B_ * C_ * D_];     // pong

// ---------------- helpers ----------------
__device__ __forceinline__ uint32_t smem_u32(const void* p) {
    uint32_t a;
    asm("{ .reg .u64 t; cvta.to.shared.u64 t, %1; cvt.u32.u64 %0, t; }" : "=r"(a) : "l"(p));
    return a;
}
__device__ __forceinline__ float tf32r(float x) {
    uint32_t u;
    asm("cvt.rna.tf32.f32 %0, %1;" : "=r"(u) : "f"(x));
    return __uint_as_float(u);
}
__device__ __forceinline__ void cp16(uint32_t dst, const void* src) {
    asm volatile("cp.async.cg.shared.global [%0], [%1], 16;" :: "r"(dst), "l"(src));
}
#define CP_COMMIT() asm volatile("cp.async.commit_group;" ::: "memory")
#define CP_WAIT1()  asm volatile("cp.async.wait_group 1;" ::: "memory")
#define CP_WAIT0()  asm volatile("cp.async.wait_group 0;" ::: "memory")

__device__ __forceinline__ void mma_tf32(float* c, const uint32_t* a, const uint32_t* b) {
    asm volatile(
        "mma.sync.aligned.m16n8k8.row.col.f32.tf32.tf32.f32 "
        "{%0,%1,%2,%3}, {%4,%5,%6,%7}, {%8,%9}, {%0,%1,%2,%3};"
        : "+f"(c[0]), "+f"(c[1]), "+f"(c[2]), "+f"(c[3])
        : "r"(a[0]), "r"(a[1]), "r"(a[2]), "r"(a[3]), "r"(b[0]), "r"(b[1]));
}

// ---------------- fista 3xTF32 mma kernel ----------------
// CTA tile 64(batch) x 128(dict); K=2048 in BK=16 chunks, 2-stage cp.async.
// hi/lo interleaved as float2 in gmem+smem -> one LDS.64 per fragment element.
// smem 60KB -> 3 CTAs/SM (24 warps/SM, 6/SMSP); grid 384 <= 444 slots: 1 wave.
// acc = xt @ M2 (3 MMAs per product: al*bh + ah*bl + ah*bh).
// v = y2 - acc, group soft-threshold + momentum, writes z (fp32) + state (hi,lo).
#define TMF 64
#define TNF 128
#define BKF 16
#define RSTR 40                       // floats per smem row (32 data + 8 pad; 40%32==8)
#define A_ST (TMF*RSTR)               // 2560 floats per stage
#define B_ST (TNF*RSTR)               // 5120 floats per stage
#define SMEM_FISTA ((2*A_ST + 2*B_ST) * 4)   // 61440 B

__global__ __launch_bounds__(256, 3) void fista_mma_k(
    const float2* __restrict__ st_in, const float* __restrict__ xo_in,
    float* __restrict__ xn_out, float2* __restrict__ st_out,
    const float2* __restrict__ M2, const float* __restrict__ y2, float mu)
{
    extern __shared__ float smem[];
    float* AS = smem;                    // [2][TMF][RSTR] interleaved (hi,lo)
    float* BS = smem + 2 * A_ST;         // [2][TNF][RSTR]

    const int tid = threadIdx.x;
    const int wid = tid >> 5, lane = tid & 31;
    const int c = blockIdx.z;
    const int row0 = blockIdx.y * TMF, col0 = blockIdx.x * TNF;
    const int wm0 = (wid >> 2) * 32;
    const int wn0 = (wid & 3) * 32;
    const int gq = lane >> 2, tq = lane & 3;

    const float2* Ag = st_in + (size_t)row0 * CD + (size_t)c * D_;
    const float2* Bg = M2 + (size_t)c * D_ * D_ + (size_t)col0 * D_;

    const uint32_t a_sm = smem_u32(AS);
    const uint32_t b_sm = smem_u32(BS);

    float acc[2][4][4];
#pragma unroll
    for (int mt = 0; mt < 2; mt++)
#pragma unroll
        for (int nt = 0; nt < 4; nt++)
#pragma unroll
            for (int q = 0; q < 4; q++) acc[mt][nt][q] = 0.f;

    // stage: A 64 rows x 8 chunks(16B) = 512; B 128 x 8 = 1024
    auto load_stage = [&](int s, int ktile) {
        const size_t ko = (size_t)ktile * BKF;
#pragma unroll
        for (int l = 0; l < 2; l++) {
            int v = tid + l * 256;
            int r = v >> 3, cc = v & 7;
            cp16(a_sm + (uint32_t)(((s * TMF + r) * RSTR + cc * 4) * 4),
                 Ag + (size_t)r * CD + ko + cc * 2);
        }
#pragma unroll
        for (int l = 0; l < 4; l++) {
            int v = tid + l * 256;
            int r = v >> 3, cc = v & 7;
            cp16(b_sm + (uint32_t)(((s * TNF + r) * RSTR + cc * 4) * 4),
                 Bg + (size_t)r * D_ + ko + cc * 2);
        }
    };

    const int NKT = D_ / BKF;  // 128
    load_stage(0, 0); CP_COMMIT();

    for (int kt = 0; kt < NKT; kt++) {
        __syncthreads();   // previous tile fully consumed before refilling its buffer
        if (kt + 1 < NKT) {
            load_stage((kt + 1) & 1, kt + 1);
            CP_COMMIT();
            CP_WAIT1();
        } else {
            CP_WAIT0();
        }
        __syncthreads();

        const float* Ab = AS + (kt & 1) * A_ST;
        const float* Bb = BS + (kt & 1) * B_ST;
#pragma unroll
        for (int ks = 0; ks < 2; ks++) {
            const int k0 = ks * 8;
            uint32_t ah[2][4], al[2][4], bh[4][2], bl[4][2];
#pragma unroll
            for (int mt = 0; mt < 2; mt++) {
                const int rb = (wm0 + mt * 16 + gq) * RSTR + (k0 + tq) * 2;
                float2 p0 = *(const float2*)(Ab + rb);
                float2 p1 = *(const float2*)(Ab + rb + 8 * RSTR);
                float2 p2 = *(const float2*)(Ab + rb + 8);
                float2 p3 = *(const float2*)(Ab + rb + 8 * RSTR + 8);
                ah[mt][0] = __float_as_uint(p0.x); al[mt][0] = __float_as_uint(p0.y);
                ah[mt][1] = __float_as_uint(p1.x); al[mt][1] = __float_as_uint(p1.y);
                ah[mt][2] = __float_as_uint(p2.x); al[mt][2] = __float_as_uint(p2.y);
                ah[mt][3] = __float_as_uint(p3.x); al[mt][3] = __float_as_uint(p3.y);
            }
#pragma unroll
            for (int nt = 0; nt < 4; nt++) {
                const int rb = (wn0 + nt * 8 + gq) * RSTR + (k0 + tq) * 2;
                float2 q0 = *(const float2*)(Bb + rb);
                float2 q1 = *(const float2*)(Bb + rb + 8);
                bh[nt][0] = __float_as_uint(q0.x); bl[nt][0] = __float_as_uint(q0.y);
                bh[nt][1] = __float_as_uint(q1.x); bl[nt][1] = __float_as_uint(q1.y);
            }
#pragma unroll
            for (int mt = 0; mt < 2; mt++)
#pragma unroll
                for (int nt = 0; nt < 4; nt++) {
                    mma_tf32(acc[mt][nt], al[mt], bh[nt]);
                    mma_tf32(acc[mt][nt], ah[mt], bl[nt]);
                    mma_tf32(acc[mt][nt], ah[mt], bh[nt]);
                }
        }
    }

    // ---- fused epilogue: v = y2 - acc ----
    const size_t cb = (size_t)c * D_;
#pragma unroll
    for (int mt = 0; mt < 2; mt++) {
        const int r0 = row0 + wm0 + mt * 16 + gq;
#pragma unroll
        for (int nt = 0; nt < 4; nt++) {
            const int col = col0 + wn0 + nt * 8 + 2 * tq;
            const size_t i0 = (size_t)r0 * CD + cb + col;
            const size_t i1 = i0 + (size_t)8 * CD;

            float2 y0 = *(const float2*)(y2 + i0);
            float2 y1 = *(const float2*)(y2 + i1);
            float v00 = y0.x - acc[mt][nt][0];
            float v01 = y0.y - acc[mt][nt][1];
            float v10 = y1.x - acc[mt][nt][2];
            float v11 = y1.y - acc[mt][nt][3];

            float ss0 = fmaf(v00, v00, v01 * v01);
            float ss1 = fmaf(v10, v10, v11 * v11);
            ss0 += __shfl_xor_sync(0xffffffffu, ss0, 1);
            ss0 += __shfl_xor_sync(0xffffffffu, ss0, 2);
            ss1 += __shfl_xor_sync(0xffffffffu, ss1, 1);
            ss1 += __shfl_xor_sync(0xffffffffu, ss1, 2);
            float sc0 = fmaxf(1.f - (LAM * TAU) / sqrtf(ss0), 0.f);
            float sc1 = fmaxf(1.f - (LAM * TAU) / sqrtf(ss1), 0.f);

            float2 xo0 = *(const float2*)(xo_in + i0);
            float2 xo1 = *(const float2*)(xo_in + i1);

            float z00 = sc0 * fmaxf(v00, 0.f);
            float z01 = sc0 * fmaxf(v01, 0.f);
            float z10 = sc1 * fmaxf(v10, 0.f);
            float z11 = sc1 * fmaxf(v11, 0.f);

            float m00 = fmaf(mu, z00 - xo0.x, z00);
            float m01 = fmaf(mu, z01 - xo0.y, z01);
            float m10 = fmaf(mu, z10 - xo1.x, z10);
            float m11 = fmaf(mu, z11 - xo1.y, z11);

            float h00 = tf32r(m00), h01 = tf32r(m01);
            float h10 = tf32r(m10), h11 = tf32r(m11);

            *(float2*)(xn_out + i0) = make_float2(z00, z01);
            *(float2*)(xn_out + i1) = make_float2(z10, z11);
            *(float4*)(st_out + i0) = make_float4(h00, tf32r(m00 - h00),
                                                  h01, tf32r(m01 - h01));
            *(float4*)(st_out + i1) = make_float4(h10, tf32r(m10 - h10),
                                                  h11, tf32r(m11 - h11));
        }
    }
}

// ---------------- elementwise helpers ----------------
__global__ void zero_init_k(float* __restrict__ z, float2* __restrict__ s, int n) {
    int i = blockIdx.x * blockDim.x + threadIdx.x;
    if (i < n) { z[i] = 0.f; s[i] = make_float2(0.f, 0.f); }
}

// G (fp32) -> M2 = TAU*G - I as interleaved (hi, lo) tf32 pair.
__global__ void make_M2_k(const float* __restrict__ g, float2* __restrict__ m2) {
    size_t i = (size_t)blockIdx.x * blockDim.x + threadIdx.x;
    if (i >= (size_t)C_ * D_ * D_) return;
    int d = (int)(i % D_);
    int e = (int)((i / D_) % D_);
    float m = TAU * g[i] - ((e == d) ? 1.f : 0.f);
    float hi = tf32r(m);
    m2[i] = make_float2(hi, tf32r(m - hi));
}

__global__ void scale_y_k(float* __restrict__ y, int n) {
    int i = blockIdx.x * blockDim.x + threadIdx.x;
    if (i < n) y[i] *= TAU;
}

// ---------------- FFMA GEMMs (Gram, y, decoder) ----------------
__global__ __launch_bounds__(256, 2) void gemm_nt_k(
    const float* __restrict__ A, int lda, size_t sA,
    const float* __restrict__ Bp, int ldb, size_t sB,
    float* __restrict__ Cp, int ldc, size_t sC, int K)
{
    const int BM = 128, BN = 128, BK = 16;
    __shared__ float As[BK][BM];
    __shared__ float Bs[BK][BN];

    A  += (size_t)blockIdx.z * sA;
    Bp += (size_t)blockIdx.z * sB;
    Cp += (size_t)blockIdx.z * sC;

    const int row0 = blockIdx.y * BM;
    const int col0 = blockIdx.x * BN;
    const int tid = threadIdx.x;
    const int tx = tid & 15;
    const int ty = tid >> 4;

    float acc[8][8];
#pragma unroll
    for (int i = 0; i < 8; i++)
#pragma unroll
        for (int j = 0; j < 8; j++) acc[i][j] = 0.f;

    for (int kt = 0; kt < K; kt += BK) {
#pragma unroll
        for (int l = 0; l < 2; l++) {
            int v = tid + l * 256;
            int m = v >> 2;
            int kq = (v & 3) << 2;
            float4 f = *(const float4*)(A + (size_t)(row0 + m) * lda + kt + kq);
            As[kq + 0][m] = f.x; As[kq + 1][m] = f.y;
            As[kq + 2][m] = f.z; As[kq + 3][m] = f.w;
        }
#pragma unroll
        for (int l = 0; l < 2; l++) {
            int v = tid + l * 256;
            int n = v >> 2;
            int kq = (v & 3) << 2;
            float4 f = *(const float4*)(Bp + (size_t)(col0 + n) * ldb + kt + kq);
            Bs[kq + 0][n] = f.x; Bs[kq + 1][n] = f.y;
            Bs[kq + 2][n] = f.z; Bs[kq + 3][n] = f.w;
        }
        __syncthreads();

#pragma unroll
        for (int k = 0; k < BK; k++) {
            float a[8], b[8];
            *(float4*)&a[0] = *(const float4*)&As[k][ty * 8];
            *(float4*)&a[4] = *(const float4*)&As[k][ty * 8 + 4];
            *(float4*)&b[0] = *(const float4*)&Bs[k][tx * 8];
            *(float4*)&b[4] = *(const float4*)&Bs[k][tx * 8 + 4];
#pragma unroll
            for (int i = 0; i < 8; i++)
#pragma unroll
                for (int j = 0; j < 8; j++)
                    acc[i][j] = fmaf(a[i], b[j], acc[i][j]);
        }
        __syncthreads();
    }

#pragma unroll
    for (int i = 0; i < 8; i++) {
        size_t base = (size_t)(row0 + ty * 8 + i) * ldc + col0 + tx * 8;
        *(float4*)&Cp[base]     = make_float4(acc[i][0], acc[i][1], acc[i][2], acc[i][3]);
        *(float4*)&Cp[base + 4] = make_float4(acc[i][4], acc[i][5], acc[i][6], acc[i][7]);
    }
}

__global__ __launch_bounds__(256, 2) void gemm_nn_dec_k(
    const float* __restrict__ Z, const float* __restrict__ W,
    float* __restrict__ Out)
{
    const int BM = 128, BN = 128, BK = 16, K = D_;
    __shared__ float As[BK][BM];
    __shared__ float Bs[BK][BN];

    const int c = blockIdx.z;
    const float* A  = Z + c * D_;
    const float* Bp = W + (size_t)c * D_ * N_;
    float* Cp = Out + c * N_;
    const int row0 = blockIdx.y * BM;
    const int col0 = blockIdx.x * BN;
    const int tid = threadIdx.x;
    const int tx = tid & 15;
    const int ty = tid >> 4;

    float acc[8][8];
#pragma unroll
    for (int i = 0; i < 8; i++)
#pragma unroll
        for (int j = 0; j < 8; j++) acc[i][j] = 0.f;

    for (int kt = 0; kt < K; kt += BK) {
#pragma unroll
        for (int l = 0; l < 2; l++) {
            int v = tid + l * 256;
            int m = v >> 2;
            int kq = (v & 3) << 2;
            float4 f = *(const float4*)(A + (size_t)(row0 + m) * CD + kt + kq);
            As[kq + 0][m] = f.x; As[kq + 1][m] = f.y;
            As[kq + 2][m] = f.z; As[kq + 3][m] = f.w;
        }
#pragma unroll
        for (int l = 0; l < 2; l++) {
            int v = tid + l * 256;
            int kr = v >> 5;
            int nq = (v & 31) << 2;
            float4 f = *(const float4*)(Bp + (size_t)(kt + kr) * N_ + col0 + nq);
            *(float4*)&Bs[kr][nq] = f;
        }
        __syncthreads();

#pragma unroll
        for (int k = 0; k < BK; k++) {
            float a[8], b[8];
            *(float4*)&a[0] = *(const float4*)&As[k][ty * 8];
            *(float4*)&a[4] = *(const float4*)&As[k][ty * 8 + 4];
            *(float4*)&b[0] = *(const float4*)&Bs[k][tx * 8];
            *(float4*)&b[4] = *(const float4*)&Bs[k][tx * 8 + 4];
#pragma unroll
            for (int i = 0; i < 8; i++)
#pragma unroll
                for (int j = 0; j < 8; j++)
                    acc[i][j] = fmaf(a[i], b[j], acc[i][j]);
        }
        __syncthreads();
    }

#pragma unroll
    for (int i = 0; i < 8; i++) {
        size_t base = (size_t)(row0 + ty * 8 + i) * CN + col0 + tx * 8;
        *(float4*)&Cp[base]     = make_float4(acc[i][0], acc[i][1], acc[i][2], acc[i][3]);
        *(float4*)&Cp[base + 4] = make_float4(acc[i][4], acc[i][5], acc[i][6], acc[i][7]);
    }
}

extern "C" void kernel_launch(void* const* d_in, const int* in_sizes, int n_in,
                              void* d_out, int out_size)
{
    const float* x = (const float*)d_in[0];
    const float* W = (const float*)d_in[1];
    if (in_sizes[0] != B_ * C_ * N_) { const float* t = x; x = W; W = t; }
    float* out = (float*)d_out;

    float *pg, *py, *pn0, *pn1;
    float2 *pm2, *ps0, *ps1;
    cudaGetSymbolAddress((void**)&pg,  g_gram);
    cudaGetSymbolAddress((void**)&pm2, g_m2);
    cudaGetSymbolAddress((void**)&py,  g_y);
    cudaGetSymbolAddress((void**)&pn0, g_n0);
    cudaGetSymbolAddress((void**)&pn1, g_n1);
    cudaGetSymbolAddress((void**)&ps0, g_s0);
    cudaGetSymbolAddress((void**)&ps1, g_s1);

    static int smem_set = 0;
    if (!smem_set) {
        cudaFuncSetAttribute(fista_mma_k, cudaFuncAttributeMaxDynamicSharedMemorySize,
                             SMEM_FISTA);
        smem_set = 1;
    }

    const int nstate = B_ * C_ * D_;
    // z_old = 0, momentum (hi,lo) = 0
    zero_init_k<<<(nstate + 255) / 256, 256>>>(pn0, ps0, nstate);

    // Gram[c] = W_c W_c^T (exact fp32)
    gemm_nt_k<<<dim3(16, 16, 3), 256>>>(W, N_, (size_t)D_ * N_,
                                        W, N_, (size_t)D_ * N_,
                                        pg, D_, (size_t)D_ * D_, N_);
    // y[b,c,d] = sum_n x W (exact fp32)
    gemm_nt_k<<<dim3(16, 4, 3), 256>>>(x, CN, (size_t)N_,
                                       W, N_, (size_t)D_ * N_,
                                       py, CD, (size_t)D_, N_);
    // M2 = TAU*G - I -> interleaved tf32 (hi, lo); y2 = TAU*y
    {
        size_t ng = (size_t)C_ * D_ * D_;
        make_M2_k<<<(unsigned)((ng + 255) / 256), 256>>>(pg, pm2);
        scale_y_k<<<(nstate + 255) / 256, 256>>>(py, nstate);
    }

    // 30 FISTA iterations: 3xTF32 split-precision tensor-core GEMM, 1 wave/iter
    float t = 1.f;
    float2 *si = ps0, *so = ps1;
    float *no = pn0, *nn = pn1;
    for (int it = 0; it < NLAYERS; it++) {
        float tnv = (1.f + sqrtf(1.f + 4.f * t * t)) * 0.5f;
        float mu = (t - 1.f) / tnv;
        fista_mma_k<<<dim3(D_ / TNF, B_ / TMF, C_), 256, SMEM_FISTA>>>(
            si, no, nn, so, pm2, py, mu);
        float2* t2 = si; si = so; so = t2;
        float* t1 = no; no = nn; nn = t1;
        t = tnv;
    }

    // decoder: out = z @ W (exact fp32); final z is in `no` after last swap
    gemm_nn_dec_k<<<dim3(8, 4, 3), 256>>>(no, W, out);
}

// round 13
// speedup vs baseline: 1.8234x; 1.8234x over previous
#include <cuda_runtime.h>
#include <cuda_bf16.h>
#include <math.h>
#include <stdint.h>

#define B_ 512
#define C_ 3
#define N_ 1024
#define D_ 2048
#define CD (C_*D_)
#define CN (C_*N_)
#define TAU 0.1f
#define LAM 0.1f
#define NLAYERS 30

// ---------------- scratch (static device globals) ----------------
__device__ float          g_gram[(size_t)C_ * D_ * D_];  // fp32 Gram temp
__device__ __nv_bfloat16  g_m2h[(size_t)C_ * D_ * D_];   // hi bf16 of M2 = TAU*G - I
__device__ __nv_bfloat16  g_m2l[(size_t)C_ * D_ * D_];   // lo bf16 of M2
__device__ float          g_y[(size_t)B_ * C_ * D_];     // y2 = TAU * y
__device__ float          g_n0[(size_t)B_ * C_ * D_];    // z state fp32, ping
__device__ float          g_n1[(size_t)B_ * C_ * D_];    // pong
__device__ __nv_bfloat16  g_sh0[(size_t)B_ * C_ * D_];   // momentum hi, ping
__device__ __nv_bfloat16  g_sh1[(size_t)B_ * C_ * D_];   // pong
__device__ __nv_bfloat16  g_sl0[(size_t)B_ * C_ * D_];   // momentum lo, ping
__device__ __nv_bfloat16  g_sl1[(size_t)B_ * C_ * D_];   // pong

// ---------------- helpers ----------------
__device__ __forceinline__ uint32_t smem_u32(const void* p) {
    uint32_t a;
    asm("{ .reg .u64 t; cvta.to.shared.u64 t, %1; cvt.u32.u64 %0, t; }" : "=r"(a) : "l"(p));
    return a;
}
__device__ __forceinline__ void cp16(uint32_t dst, const void* src) {
    asm volatile("cp.async.cg.shared.global [%0], [%1], 16;" :: "r"(dst), "l"(src));
}
#define CP_COMMIT() asm volatile("cp.async.commit_group;" ::: "memory")
#define CP_WAIT1()  asm volatile("cp.async.wait_group 1;" ::: "memory")
#define CP_WAIT0()  asm volatile("cp.async.wait_group 0;" ::: "memory")

__device__ __forceinline__ void mma_bf16(float* c, const uint32_t* a, const uint32_t* b) {
    asm volatile(
        "mma.sync.aligned.m16n8k16.row.col.f32.bf16.bf16.f32 "
        "{%0,%1,%2,%3}, {%4,%5,%6,%7}, {%8,%9}, {%0,%1,%2,%3};"
        : "+f"(c[0]), "+f"(c[1]), "+f"(c[2]), "+f"(c[3])
        : "r"(a[0]), "r"(a[1]), "r"(a[2]), "r"(a[3]), "r"(b[0]), "r"(b[1]));
}
__device__ __forceinline__ uint32_t lds32(const __nv_bfloat16* p) {
    return *(const uint32_t*)p;
}

// ---------------- fista 3xBF16 mma kernel ----------------
// CTA tile 64(batch) x 128(dict); K=2048 in BK=32 chunks, 2-stage cp.async.
// Operands: separate bf16 hi/lo planes (k-contiguous for mma packing).
// acc = xt @ M2 via al*bh + ah*bl + ah*bh (m16n8k16 bf16, fp32 accum).
// smem ~60KB -> 3 CTAs/SM; grid 384 <= 444 slots: one wave.
// v = y2 - acc, group soft-threshold + momentum, writes z (fp32) + bf16 hi/lo state.
#define TMF 64
#define TNF 128
#define BKF 32
#define STR 40                         // bf16 per smem row (32 data + 8 pad; 80B rows)
#define A_ST (TMF*STR)                 // 2560 bf16 per stage
#define B_ST (TNF*STR)                 // 5120 bf16 per stage
#define SMEM_FISTA ((2*A_ST + 2*A_ST + 2*B_ST + 2*B_ST) * 2)  // 61440 B

__global__ __launch_bounds__(256, 3) void fista_mma_k(
    const __nv_bfloat16* __restrict__ sh_in, const __nv_bfloat16* __restrict__ sl_in,
    const float* __restrict__ xo_in,
    float* __restrict__ xn_out,
    __nv_bfloat16* __restrict__ sh_out, __nv_bfloat16* __restrict__ sl_out,
    const __nv_bfloat16* __restrict__ M2h, const __nv_bfloat16* __restrict__ M2l,
    const float* __restrict__ y2, float mu)
{
    extern __shared__ __nv_bfloat16 smem[];
    __nv_bfloat16* AH = smem;                       // [2][TMF][STR]
    __nv_bfloat16* AL = smem + 2 * A_ST;
    __nv_bfloat16* BH = smem + 4 * A_ST;            // [2][TNF][STR]
    __nv_bfloat16* BL = smem + 4 * A_ST + 2 * B_ST;

    const int tid = threadIdx.x;
    const int wid = tid >> 5, lane = tid & 31;
    const int c = blockIdx.z;
    const int row0 = blockIdx.y * TMF, col0 = blockIdx.x * TNF;
    const int wm0 = (wid >> 2) * 32;
    const int wn0 = (wid & 3) * 32;
    const int gq = lane >> 2, tq = lane & 3;

    const __nv_bfloat16* AgH = sh_in + (size_t)row0 * CD + (size_t)c * D_;
    const __nv_bfloat16* AgL = sl_in + (size_t)row0 * CD + (size_t)c * D_;
    const __nv_bfloat16* BgH = M2h + (size_t)c * D_ * D_ + (size_t)col0 * D_;
    const __nv_bfloat16* BgL = M2l + (size_t)c * D_ * D_ + (size_t)col0 * D_;

    const uint32_t ah_sm = smem_u32(AH);
    const uint32_t al_sm = smem_u32(AL);
    const uint32_t bh_sm = smem_u32(BH);
    const uint32_t bl_sm = smem_u32(BL);

    float acc[2][4][4];
#pragma unroll
    for (int mt = 0; mt < 2; mt++)
#pragma unroll
        for (int nt = 0; nt < 4; nt++)
#pragma unroll
            for (int q = 0; q < 4; q++) acc[mt][nt][q] = 0.f;

    // stage: A 64 rows x 4 chunks(16B=8 bf16) = 256 per plane; B 128 x 4 = 512
    auto load_stage = [&](int s, int ktile) {
        const size_t ko = (size_t)ktile * BKF;
        {
            int r = tid >> 2, cc = tid & 3;
            uint32_t so = (uint32_t)(((s * TMF + r) * STR + cc * 8) * 2);
            size_t go = (size_t)r * CD + ko + cc * 8;
            cp16(ah_sm + so, AgH + go);
            cp16(al_sm + so, AgL + go);
        }
#pragma unroll
        for (int l = 0; l < 2; l++) {
            int v = tid + l * 256;
            int r = v >> 2, cc = v & 3;
            uint32_t so = (uint32_t)(((s * TNF + r) * STR + cc * 8) * 2);
            size_t go = (size_t)r * D_ + ko + cc * 8;
            cp16(bh_sm + so, BgH + go);
            cp16(bl_sm + so, BgL + go);
        }
    };

    const int NKT = D_ / BKF;  // 64
    load_stage(0, 0); CP_COMMIT();

    for (int kt = 0; kt < NKT; kt++) {
        __syncthreads();   // prior tile fully consumed before refilling its buffer
        if (kt + 1 < NKT) {
            load_stage((kt + 1) & 1, kt + 1);
            CP_COMMIT();
            CP_WAIT1();
        } else {
            CP_WAIT0();
        }
        __syncthreads();

        const __nv_bfloat16* AbH = AH + (kt & 1) * A_ST;
        const __nv_bfloat16* AbL = AL + (kt & 1) * A_ST;
        const __nv_bfloat16* BbH = BH + (kt & 1) * B_ST;
        const __nv_bfloat16* BbL = BL + (kt & 1) * B_ST;
#pragma unroll
        for (int ks = 0; ks < 2; ks++) {
            const int k0 = ks * 16;
            uint32_t ah[2][4], al[2][4], bh[4][2], bl[4][2];
#pragma unroll
            for (int mt = 0; mt < 2; mt++) {
                const int rb = (wm0 + mt * 16 + gq) * STR + k0 + 2 * tq;
                ah[mt][0] = lds32(AbH + rb);
                ah[mt][1] = lds32(AbH + rb + 8 * STR);
                ah[mt][2] = lds32(AbH + rb + 8);
                ah[mt][3] = lds32(AbH + rb + 8 * STR + 8);
                al[mt][0] = lds32(AbL + rb);
                al[mt][1] = lds32(AbL + rb + 8 * STR);
                al[mt][2] = lds32(AbL + rb + 8);
                al[mt][3] = lds32(AbL + rb + 8 * STR + 8);
            }
#pragma unroll
            for (int nt = 0; nt < 4; nt++) {
                const int rb = (wn0 + nt * 8 + gq) * STR + k0 + 2 * tq;
                bh[nt][0] = lds32(BbH + rb);
                bh[nt][1] = lds32(BbH + rb + 8);
                bl[nt][0] = lds32(BbL + rb);
                bl[nt][1] = lds32(BbL + rb + 8);
            }
#pragma unroll
            for (int mt = 0; mt < 2; mt++)
#pragma unroll
                for (int nt = 0; nt < 4; nt++) {
                    mma_bf16(acc[mt][nt], al[mt], bh[nt]);
                    mma_bf16(acc[mt][nt], ah[mt], bl[nt]);
                    mma_bf16(acc[mt][nt], ah[mt], bh[nt]);
                }
        }
    }

    // ---- fused epilogue: v = y2 - acc ----
    const size_t cb = (size_t)c * D_;
#pragma unroll
    for (int mt = 0; mt < 2; mt++) {
        const int r0 = row0 + wm0 + mt * 16 + gq;
#pragma unroll
        for (int nt = 0; nt < 4; nt++) {
            const int col = col0 + wn0 + nt * 8 + 2 * tq;
            const size_t i0 = (size_t)r0 * CD + cb + col;
            const size_t i1 = i0 + (size_t)8 * CD;

            float2 y0 = *(const float2*)(y2 + i0);
            float2 y1 = *(const float2*)(y2 + i1);
            float v00 = y0.x - acc[mt][nt][0];
            float v01 = y0.y - acc[mt][nt][1];
            float v10 = y1.x - acc[mt][nt][2];
            float v11 = y1.y - acc[mt][nt][3];

            float ss0 = fmaf(v00, v00, v01 * v01);
            float ss1 = fmaf(v10, v10, v11 * v11);
            ss0 += __shfl_xor_sync(0xffffffffu, ss0, 1);
            ss0 += __shfl_xor_sync(0xffffffffu, ss0, 2);
            ss1 += __shfl_xor_sync(0xffffffffu, ss1, 1);
            ss1 += __shfl_xor_sync(0xffffffffu, ss1, 2);
            float sc0 = fmaxf(1.f - (LAM * TAU) / sqrtf(ss0), 0.f);
            float sc1 = fmaxf(1.f - (LAM * TAU) / sqrtf(ss1), 0.f);

            float2 xo0 = *(const float2*)(xo_in + i0);
            float2 xo1 = *(const float2*)(xo_in + i1);

            float z00 = sc0 * fmaxf(v00, 0.f);
            float z01 = sc0 * fmaxf(v01, 0.f);
            float z10 = sc1 * fmaxf(v10, 0.f);
            float z11 = sc1 * fmaxf(v11, 0.f);

            float m00 = fmaf(mu, z00 - xo0.x, z00);
            float m01 = fmaf(mu, z01 - xo0.y, z01);
            float m10 = fmaf(mu, z10 - xo1.x, z10);
            float m11 = fmaf(mu, z11 - xo1.y, z11);

            __nv_bfloat16 h00 = __float2bfloat16_rn(m00);
            __nv_bfloat16 h01 = __float2bfloat16_rn(m01);
            __nv_bfloat16 h10 = __float2bfloat16_rn(m10);
            __nv_bfloat16 h11 = __float2bfloat16_rn(m11);
            __nv_bfloat162 hv0; hv0.x = h00; hv0.y = h01;
            __nv_bfloat162 hv1; hv1.x = h10; hv1.y = h11;
            __nv_bfloat162 lv0;
            lv0.x = __float2bfloat16_rn(m00 - __bfloat162float(h00));
            lv0.y = __float2bfloat16_rn(m01 - __bfloat162float(h01));
            __nv_bfloat162 lv1;
            lv1.x = __float2bfloat16_rn(m10 - __bfloat162float(h10));
            lv1.y = __float2bfloat16_rn(m11 - __bfloat162float(h11));

            *(float2*)(xn_out + i0) = make_float2(z00, z01);
            *(float2*)(xn_out + i1) = make_float2(z10, z11);
            *(__nv_bfloat162*)(sh_out + i0) = hv0;
            *(__nv_bfloat162*)(sh_out + i1) = hv1;
            *(__nv_bfloat162*)(sl_out + i0) = lv0;
            *(__nv_bfloat162*)(sl_out + i1) = lv1;
        }
    }
}

// ---------------- elementwise helpers ----------------
__global__ void zero_init_k(float* __restrict__ z,
                            __nv_bfloat16* __restrict__ sh,
                            __nv_bfloat16* __restrict__ sl, int n) {
    int i = blockIdx.x * blockDim.x + threadIdx.x;
    if (i < n) { z[i] = 0.f; sh[i] = __float2bfloat16_rn(0.f); sl[i] = __float2bfloat16_rn(0.f); }
}

// G (fp32) -> M2 = TAU*G - I as separate bf16 hi/lo planes.
__global__ void make_M2_k(const float* __restrict__ g,
                          __nv_bfloat16* __restrict__ m2h,
                          __nv_bfloat16* __restrict__ m2l) {
    size_t i = (size_t)blockIdx.x * blockDim.x + threadIdx.x;
    if (i >= (size_t)C_ * D_ * D_) return;
    int d = (int)(i % D_);
    int e = (int)((i / D_) % D_);
    float m = TAU * g[i] - ((e == d) ? 1.f : 0.f);
    __nv_bfloat16 hi = __float2bfloat16_rn(m);
    m2h[i] = hi;
    m2l[i] = __float2bfloat16_rn(m - __bfloat162float(hi));
}

__global__ void scale_y_k(float* __restrict__ y, int n) {
    int i = blockIdx.x * blockDim.x + threadIdx.x;
    if (i < n) y[i] *= TAU;
}

// ---------------- FFMA GEMMs (Gram, y, decoder) ----------------
__global__ __launch_bounds__(256, 2) void gemm_nt_k(
    const float* __restrict__ A, int lda, size_t sA,
    const float* __restrict__ Bp, int ldb, size_t sB,
    float* __restrict__ Cp, int ldc, size_t sC, int K)
{
    const int BM = 128, BN = 128, BK = 16;
    __shared__ float As[BK][BM];
    __shared__ float Bs[BK][BN];

    A  += (size_t)blockIdx.z * sA;
    Bp += (size_t)blockIdx.z * sB;
    Cp += (size_t)blockIdx.z * sC;

    const int row0 = blockIdx.y * BM;
    const int col0 = blockIdx.x * BN;
    const int tid = threadIdx.x;
    const int tx = tid & 15;
    const int ty = tid >> 4;

    float acc[8][8];
#pragma unroll
    for (int i = 0; i < 8; i++)
#pragma unroll
        for (int j = 0; j < 8; j++) acc[i][j] = 0.f;

    for (int kt = 0; kt < K; kt += BK) {
#pragma unroll
        for (int l = 0; l < 2; l++) {
            int v = tid + l * 256;
            int m = v >> 2;
            int kq = (v & 3) << 2;
            float4 f = *(const float4*)(A + (size_t)(row0 + m) * lda + kt + kq);
            As[kq + 0][m] = f.x; As[kq + 1][m] = f.y;
            As[kq + 2][m] = f.z; As[kq + 3][m] = f.w;
        }
#pragma unroll
        for (int l = 0; l < 2; l++) {
            int v = tid + l * 256;
            int n = v >> 2;
            int kq = (v & 3) << 2;
            float4 f = *(const float4*)(Bp + (size_t)(col0 + n) * ldb + kt + kq);
            Bs[kq + 0][n] = f.x; Bs[kq + 1][n] = f.y;
            Bs[kq + 2][n] = f.z; Bs[kq + 3][n] = f.w;
        }
        __syncthreads();

#pragma unroll
        for (int k = 0; k < BK; k++) {
            float a[8], b[8];
            *(float4*)&a[0] = *(const float4*)&As[k][ty * 8];
            *(float4*)&a[4] = *(const float4*)&As[k][ty * 8 + 4];
            *(float4*)&b[0] = *(const float4*)&Bs[k][tx * 8];
            *(float4*)&b[4] = *(const float4*)&Bs[k][tx * 8 + 4];
#pragma unroll
            for (int i = 0; i < 8; i++)
#pragma unroll
                for (int j = 0; j < 8; j++)
                    acc[i][j] = fmaf(a[i], b[j], acc[i][j]);
        }
        __syncthreads();
    }

#pragma unroll
    for (int i = 0; i < 8; i++) {
        size_t base = (size_t)(row0 + ty * 8 + i) * ldc + col0 + tx * 8;
        *(float4*)&Cp[base]     = make_float4(acc[i][0], acc[i][1], acc[i][2], acc[i][3]);
        *(float4*)&Cp[base + 4] = make_float4(acc[i][4], acc[i][5], acc[i][6], acc[i][7]);
    }
}

__global__ __launch_bounds__(256, 2) void gemm_nn_dec_k(
    const float* __restrict__ Z, const float* __restrict__ W,
    float* __restrict__ Out)
{
    const int BM = 128, BN = 128, BK = 16, K = D_;
    __shared__ float As[BK][BM];
    __shared__ float Bs[BK][BN];

    const int c = blockIdx.z;
    const float* A  = Z + c * D_;
    const float* Bp = W + (size_t)c * D_ * N_;
    float* Cp = Out + c * N_;
    const int row0 = blockIdx.y * BM;
    const int col0 = blockIdx.x * BN;
    const int tid = threadIdx.x;
    const int tx = tid & 15;
    const int ty = tid >> 4;

    float acc[8][8];
#pragma unroll
    for (int i = 0; i < 8; i++)
#pragma unroll
        for (int j = 0; j < 8; j++) acc[i][j] = 0.f;

    for (int kt = 0; kt < K; kt += BK) {
#pragma unroll
        for (int l = 0; l < 2; l++) {
            int v = tid + l * 256;
            int m = v >> 2;
            int kq = (v & 3) << 2;
            float4 f = *(const float4*)(A + (size_t)(row0 + m) * CD + kt + kq);
            As[kq + 0][m] = f.x; As[kq + 1][m] = f.y;
            As[kq + 2][m] = f.z; As[kq + 3][m] = f.w;
        }
#pragma unroll
        for (int l = 0; l < 2; l++) {
            int v = tid + l * 256;
            int kr = v >> 5;
            int nq = (v & 31) << 2;
            float4 f = *(const float4*)(Bp + (size_t)(kt + kr) * N_ + col0 + nq);
            *(float4*)&Bs[kr][nq] = f;
        }
        __syncthreads();

#pragma unroll
        for (int k = 0; k < BK; k++) {
            float a[8], b[8];
            *(float4*)&a[0] = *(const float4*)&As[k][ty * 8];
            *(float4*)&a[4] = *(const float4*)&As[k][ty * 8 + 4];
            *(float4*)&b[0] = *(const float4*)&Bs[k][tx * 8];
            *(float4*)&b[4] = *(const float4*)&Bs[k][tx * 8 + 4];
#pragma unroll
            for (int i = 0; i < 8; i++)
#pragma unroll
                for (int j = 0; j < 8; j++)
                    acc[i][j] = fmaf(a[i], b[j], acc[i][j]);
        }
        __syncthreads();
    }

#pragma unroll
    for (int i = 0; i < 8; i++) {
        size_t base = (size_t)(row0 + ty * 8 + i) * CN + col0 + tx * 8;
        *(float4*)&Cp[base]     = make_float4(acc[i][0], acc[i][1], acc[i][2], acc[i][3]);
        *(float4*)&Cp[base + 4] = make_float4(acc[i][4], acc[i][5], acc[i][6], acc[i][7]);
    }
}

extern "C" void kernel_launch(void* const* d_in, const int* in_sizes, int n_in,
                              void* d_out, int out_size)
{
    const float* x = (const float*)d_in[0];
    const float* W = (const float*)d_in[1];
    if (in_sizes[0] != B_ * C_ * N_) { const float* t = x; x = W; W = t; }
    float* out = (float*)d_out;

    float *pg, *py, *pn0, *pn1;
    __nv_bfloat16 *pm2h, *pm2l, *psh0, *psh1, *psl0, *psl1;
    cudaGetSymbolAddress((void**)&pg,   g_gram);
    cudaGetSymbolAddress((void**)&pm2h, g_m2h);
    cudaGetSymbolAddress((void**)&pm2l, g_m2l);
    cudaGetSymbolAddress((void**)&py,   g_y);
    cudaGetSymbolAddress((void**)&pn0,  g_n0);
    cudaGetSymbolAddress((void**)&pn1,  g_n1);
    cudaGetSymbolAddress((void**)&psh0, g_sh0);
    cudaGetSymbolAddress((void**)&psh1, g_sh1);
    cudaGetSymbolAddress((void**)&psl0, g_sl0);
    cudaGetSymbolAddress((void**)&psl1, g_sl1);

    static int smem_set = 0;
    if (!smem_set) {
        cudaFuncSetAttribute(fista_mma_k, cudaFuncAttributeMaxDynamicSharedMemorySize,
                             SMEM_FISTA);
        smem_set = 1;
    }

    const int nstate = B_ * C_ * D_;
    zero_init_k<<<(nstate + 255) / 256, 256>>>(pn0, psh0, psl0, nstate);

    // Gram[c] = W_c W_c^T (exact fp32)
    gemm_nt_k<<<dim3(16, 16, 3), 256>>>(W, N_, (size_t)D_ * N_,
                                        W, N_, (size_t)D_ * N_,
                                        pg, D_, (size_t)D_ * D_, N_);
    // y[b,c,d] = sum_n x W (exact fp32)
    gemm_nt_k<<<dim3(16, 4, 3), 256>>>(x, CN, (size_t)N_,
                                       W, N_, (size_t)D_ * N_,
                                       py, CD, (size_t)D_, N_);
    // M2 = TAU*G - I -> bf16 hi/lo planes; y2 = TAU*y
    {
        size_t ng = (size_t)C_ * D_ * D_;
        make_M2_k<<<(unsigned)((ng + 255) / 256), 256>>>(pg, pm2h, pm2l);
        scale_y_k<<<(nstate + 255) / 256, 256>>>(py, nstate);
    }

    // 30 FISTA iterations: 3xBF16 split-precision tensor-core GEMM, one wave/iter
    float t = 1.f;
    __nv_bfloat16 *shi = psh0, *sli = psl0, *sho = psh1, *slo = psl1;
    float *no = pn0, *nn = pn1;
    for (int it = 0; it < NLAYERS; it++) {
        float tnv = (1.f + sqrtf(1.f + 4.f * t * t)) * 0.5f;
        float mu = (t - 1.f) / tnv;
        fista_mma_k<<<dim3(D_ / TNF, B_ / TMF, C_), 256, SMEM_FISTA>>>(
            shi, sli, no, nn, sho, slo, pm2h, pm2l, py, mu);
        __nv_bfloat16* tb;
        tb = shi; shi = sho; sho = tb;
        tb = sli; sli = slo; slo = tb;
        float* t1 = no; no = nn; nn = t1;
        t = tnv;
    }

    // decoder: out = z @ W (exact fp32); final z in `no` after last swap
    gemm_nn_dec_k<<<dim3(8, 4, 3), 256>>>(no, W, out);
}

// round 15
// speedup vs baseline: 2.0223x; 1.1091x over previous
#include <cuda_runtime.h>
#include <cuda_bf16.h>
#include <math.h>
#include <stdint.h>

#define B_ 512
#define C_ 3
#define N_ 1024
#define D_ 2048
#define CD (C_*D_)
#define CN (C_*N_)
#define TAU 0.1f
#define LAM 0.1f
#define NLAYERS 30

// ---------------- scratch (static device globals) ----------------
__device__ float          g_gram[(size_t)C_ * D_ * D_];  // fp32 Gram temp
__device__ __nv_bfloat16  g_m2h[(size_t)C_ * D_ * D_];   // hi bf16 of M2 = TAU*G - I
__device__ __nv_bfloat16  g_m2l[(size_t)C_ * D_ * D_];   // lo bf16 of M2
__device__ float          g_y[(size_t)B_ * C_ * D_];     // y2 = TAU * y
__device__ float          g_n0[(size_t)B_ * C_ * D_];    // z state fp32, ping
__device__ float          g_n1[(size_t)B_ * C_ * D_];    // pong
__device__ __nv_bfloat16  g_sh0[(size_t)B_ * C_ * D_];   // momentum hi, ping
__device__ __nv_bfloat16  g_sh1[(size_t)B_ * C_ * D_];   // pong
__device__ __nv_bfloat16  g_sl0[(size_t)B_ * C_ * D_];   // momentum lo, ping
__device__ __nv_bfloat16  g_sl1[(size_t)B_ * C_ * D_];   // pong
__device__ __nv_bfloat16  g_wh[(size_t)C_ * D_ * N_];    // W split hi
__device__ __nv_bfloat16  g_wl[(size_t)C_ * D_ * N_];    // W split lo
__device__ __nv_bfloat16  g_xh[(size_t)B_ * C_ * N_];    // x split hi
__device__ __nv_bfloat16  g_xl[(size_t)B_ * C_ * N_];    // x split lo

// ---------------- helpers ----------------
__device__ __forceinline__ uint32_t smem_u32(const void* p) {
    uint32_t a;
    asm("{ .reg .u64 t; cvta.to.shared.u64 t, %1; cvt.u32.u64 %0, t; }" : "=r"(a) : "l"(p));
    return a;
}
__device__ __forceinline__ void cp16(uint32_t dst, const void* src) {
    asm volatile("cp.async.cg.shared.global [%0], [%1], 16;" :: "r"(dst), "l"(src));
}
#define CP_COMMIT() asm volatile("cp.async.commit_group;" ::: "memory")
#define CP_WAIT1()  asm volatile("cp.async.wait_group 1;" ::: "memory")
#define CP_WAIT0()  asm volatile("cp.async.wait_group 0;" ::: "memory")

__device__ __forceinline__ void mma_bf16(float* c, const uint32_t* a, const uint32_t* b) {
    asm volatile(
        "mma.sync.aligned.m16n8k16.row.col.f32.bf16.bf16.f32 "
        "{%0,%1,%2,%3}, {%4,%5,%6,%7}, {%8,%9}, {%0,%1,%2,%3};"
        : "+f"(c[0]), "+f"(c[1]), "+f"(c[2]), "+f"(c[3])
        : "r"(a[0]), "r"(a[1]), "r"(a[2]), "r"(a[3]), "r"(b[0]), "r"(b[1]));
}
__device__ __forceinline__ uint32_t lds32(const __nv_bfloat16* p) {
    return *(const uint32_t*)p;
}

// ---------------- shared tile config (fista + generic 3xbf16 GEMM) ----------------
#define TMF 64
#define TNF 128
#define BKF 32
#define STR 40                         // bf16 per smem row (32 data + 8 pad; 80B rows)
#define A_ST (TMF*STR)                 // 2560 bf16 per stage
#define B_ST (TNF*STR)                 // 5120 bf16 per stage
#define SMEM_FISTA ((4*A_ST + 4*B_ST) * 2)  // 61440 B

// ============================================================================
// fista 3xBF16 mma kernel (unchanged from R13 winner)
// ============================================================================
__global__ __launch_bounds__(256, 3) void fista_mma_k(
    const __nv_bfloat16* __restrict__ sh_in, const __nv_bfloat16* __restrict__ sl_in,
    const float* __restrict__ xo_in,
    float* __restrict__ xn_out,
    __nv_bfloat16* __restrict__ sh_out, __nv_bfloat16* __restrict__ sl_out,
    const __nv_bfloat16* __restrict__ M2h, const __nv_bfloat16* __restrict__ M2l,
    const float* __restrict__ y2, float mu)
{
    extern __shared__ __nv_bfloat16 smem[];
    __nv_bfloat16* AH = smem;                       // [2][TMF][STR]
    __nv_bfloat16* AL = smem + 2 * A_ST;
    __nv_bfloat16* BH = smem + 4 * A_ST;            // [2][TNF][STR]
    __nv_bfloat16* BL = smem + 4 * A_ST + 2 * B_ST;

    const int tid = threadIdx.x;
    const int wid = tid >> 5, lane = tid & 31;
    const int c = blockIdx.z;
    const int row0 = blockIdx.y * TMF, col0 = blockIdx.x * TNF;
    const int wm0 = (wid >> 2) * 32;
    const int wn0 = (wid & 3) * 32;
    const int gq = lane >> 2, tq = lane & 3;

    const __nv_bfloat16* AgH = sh_in + (size_t)row0 * CD + (size_t)c * D_;
    const __nv_bfloat16* AgL = sl_in + (size_t)row0 * CD + (size_t)c * D_;
    const __nv_bfloat16* BgH = M2h + (size_t)c * D_ * D_ + (size_t)col0 * D_;
    const __nv_bfloat16* BgL = M2l + (size_t)c * D_ * D_ + (size_t)col0 * D_;

    const uint32_t ah_sm = smem_u32(AH);
    const uint32_t al_sm = smem_u32(AL);
    const uint32_t bh_sm = smem_u32(BH);
    const uint32_t bl_sm = smem_u32(BL);

    float acc[2][4][4];
#pragma unroll
    for (int mt = 0; mt < 2; mt++)
#pragma unroll
        for (int nt = 0; nt < 4; nt++)
#pragma unroll
            for (int q = 0; q < 4; q++) acc[mt][nt][q] = 0.f;

    auto load_stage = [&](int s, int ktile) {
        const size_t ko = (size_t)ktile * BKF;
        {
            int r = tid >> 2, cc = tid & 3;
            uint32_t so = (uint32_t)(((s * TMF + r) * STR + cc * 8) * 2);
            size_t go = (size_t)r * CD + ko + cc * 8;
            cp16(ah_sm + so, AgH + go);
            cp16(al_sm + so, AgL + go);
        }
#pragma unroll
        for (int l = 0; l < 2; l++) {
            int v = tid + l * 256;
            int r = v >> 2, cc = v & 3;
            uint32_t so = (uint32_t)(((s * TNF + r) * STR + cc * 8) * 2);
            size_t go = (size_t)r * D_ + ko + cc * 8;
            cp16(bh_sm + so, BgH + go);
            cp16(bl_sm + so, BgL + go);
        }
    };

    const int NKT = D_ / BKF;  // 64
    load_stage(0, 0); CP_COMMIT();

    for (int kt = 0; kt < NKT; kt++) {
        __syncthreads();
        if (kt + 1 < NKT) {
            load_stage((kt + 1) & 1, kt + 1);
            CP_COMMIT();
            CP_WAIT1();
        } else {
            CP_WAIT0();
        }
        __syncthreads();

        const __nv_bfloat16* AbH = AH + (kt & 1) * A_ST;
        const __nv_bfloat16* AbL = AL + (kt & 1) * A_ST;
        const __nv_bfloat16* BbH = BH + (kt & 1) * B_ST;
        const __nv_bfloat16* BbL = BL + (kt & 1) * B_ST;
#pragma unroll
        for (int ks = 0; ks < 2; ks++) {
            const int k0 = ks * 16;
            uint32_t ah[2][4], al[2][4], bh[4][2], bl[4][2];
#pragma unroll
            for (int mt = 0; mt < 2; mt++) {
                const int rb = (wm0 + mt * 16 + gq) * STR + k0 + 2 * tq;
                ah[mt][0] = lds32(AbH + rb);
                ah[mt][1] = lds32(AbH + rb + 8 * STR);
                ah[mt][2] = lds32(AbH + rb + 8);
                ah[mt][3] = lds32(AbH + rb + 8 * STR + 8);
                al[mt][0] = lds32(AbL + rb);
                al[mt][1] = lds32(AbL + rb + 8 * STR);
                al[mt][2] = lds32(AbL + rb + 8);
                al[mt][3] = lds32(AbL + rb + 8 * STR + 8);
            }
#pragma unroll
            for (int nt = 0; nt < 4; nt++) {
                const int rb = (wn0 + nt * 8 + gq) * STR + k0 + 2 * tq;
                bh[nt][0] = lds32(BbH + rb);
                bh[nt][1] = lds32(BbH + rb + 8);
                bl[nt][0] = lds32(BbL + rb);
                bl[nt][1] = lds32(BbL + rb + 8);
            }
#pragma unroll
            for (int mt = 0; mt < 2; mt++)
#pragma unroll
                for (int nt = 0; nt < 4; nt++) {
                    mma_bf16(acc[mt][nt], al[mt], bh[nt]);
                    mma_bf16(acc[mt][nt], ah[mt], bl[nt]);
                    mma_bf16(acc[mt][nt], ah[mt], bh[nt]);
                }
        }
    }

    // ---- fused epilogue: v = y2 - acc ----
    const size_t cb = (size_t)c * D_;
#pragma unroll
    for (int mt = 0; mt < 2; mt++) {
        const int r0 = row0 + wm0 + mt * 16 + gq;
#pragma unroll
        for (int nt = 0; nt < 4; nt++) {
            const int col = col0 + wn0 + nt * 8 + 2 * tq;
            const size_t i0 = (size_t)r0 * CD + cb + col;
            const size_t i1 = i0 + (size_t)8 * CD;

            float2 y0 = *(const float2*)(y2 + i0);
            float2 y1 = *(const float2*)(y2 + i1);
            float v00 = y0.x - acc[mt][nt][0];
            float v01 = y0.y - acc[mt][nt][1];
            float v10 = y1.x - acc[mt][nt][2];
            float v11 = y1.y - acc[mt][nt][3];

            float ss0 = fmaf(v00, v00, v01 * v01);
            float ss1 = fmaf(v10, v10, v11 * v11);
            ss0 += __shfl_xor_sync(0xffffffffu, ss0, 1);
            ss0 += __shfl_xor_sync(0xffffffffu, ss0, 2);
            ss1 += __shfl_xor_sync(0xffffffffu, ss1, 1);
            ss1 += __shfl_xor_sync(0xffffffffu, ss1, 2);
            float sc0 = fmaxf(1.f - (LAM * TAU) / sqrtf(ss0), 0.f);
            float sc1 = fmaxf(1.f - (LAM * TAU) / sqrtf(ss1), 0.f);

            float2 xo0 = *(const float2*)(xo_in + i0);
            float2 xo1 = *(const float2*)(xo_in + i1);

            float z00 = sc0 * fmaxf(v00, 0.f);
            float z01 = sc0 * fmaxf(v01, 0.f);
            float z10 = sc1 * fmaxf(v10, 0.f);
            float z11 = sc1 * fmaxf(v11, 0.f);

            float m00 = fmaf(mu, z00 - xo0.x, z00);
            float m01 = fmaf(mu, z01 - xo0.y, z01);
            float m10 = fmaf(mu, z10 - xo1.x, z10);
            float m11 = fmaf(mu, z11 - xo1.y, z11);

            __nv_bfloat16 h00 = __float2bfloat16_rn(m00);
            __nv_bfloat16 h01 = __float2bfloat16_rn(m01);
            __nv_bfloat16 h10 = __float2bfloat16_rn(m10);
            __nv_bfloat16 h11 = __float2bfloat16_rn(m11);
            __nv_bfloat162 hv0; hv0.x = h00; hv0.y = h01;
            __nv_bfloat162 hv1; hv1.x = h10; hv1.y = h11;
            __nv_bfloat162 lv0;
            lv0.x = __float2bfloat16_rn(m00 - __bfloat162float(h00));
            lv0.y = __float2bfloat16_rn(m01 - __bfloat162float(h01));
            __nv_bfloat162 lv1;
            lv1.x = __float2bfloat16_rn(m10 - __bfloat162float(h10));
            lv1.y = __float2bfloat16_rn(m11 - __bfloat162float(h11));

            *(float2*)(xn_out + i0) = make_float2(z00, z01);
            *(float2*)(xn_out + i1) = make_float2(z10, z11);
            *(__nv_bfloat162*)(sh_out + i0) = hv0;
            *(__nv_bfloat162*)(sh_out + i1) = hv1;
            *(__nv_bfloat162*)(sl_out + i0) = lv0;
            *(__nv_bfloat162*)(sl_out + i1) = lv1;
        }
    }
}

// ============================================================================
// Generic 3xBF16 split NT GEMM: C[z][i,j] = sum_k A[z][i,k] * B[z][j,k]  (fp32 out)
// Same tile/pipeline as fista_mma_k; plain store epilogue. Dims multiple of tile.
// ============================================================================
__global__ __launch_bounds__(256, 3) void gemm3_nt_k(
    const __nv_bfloat16* __restrict__ Ah, const __nv_bfloat16* __restrict__ Al,
    int lda, size_t sA,
    const __nv_bfloat16* __restrict__ Bh, const __nv_bfloat16* __restrict__ Bl,
    int ldb, size_t sB,
    float* __restrict__ Cp, int ldc, size_t sC, int K)
{
    extern __shared__ __nv_bfloat16 smem[];
    __nv_bfloat16* AH = smem;
    __nv_bfloat16* AL = smem + 2 * A_ST;
    __nv_bfloat16* BH = smem + 4 * A_ST;
    __nv_bfloat16* BL = smem + 4 * A_ST + 2 * B_ST;

    const int tid = threadIdx.x;
    const int wid = tid >> 5, lane = tid & 31;
    const int row0 = blockIdx.y * TMF, col0 = blockIdx.x * TNF;
    const int wm0 = (wid >> 2) * 32;
    const int wn0 = (wid & 3) * 32;
    const int gq = lane >> 2, tq = lane & 3;

    const __nv_bfloat16* AgH = Ah + (size_t)blockIdx.z * sA + (size_t)row0 * lda;
    const __nv_bfloat16* AgL = Al + (size_t)blockIdx.z * sA + (size_t)row0 * lda;
    const __nv_bfloat16* BgH = Bh + (size_t)blockIdx.z * sB + (size_t)col0 * ldb;
    const __nv_bfloat16* BgL = Bl + (size_t)blockIdx.z * sB + (size_t)col0 * ldb;
    float* Cb = Cp + (size_t)blockIdx.z * sC;

    const uint32_t ah_sm = smem_u32(AH);
    const uint32_t al_sm = smem_u32(AL);
    const uint32_t bh_sm = smem_u32(BH);
    const uint32_t bl_sm = smem_u32(BL);

    float acc[2][4][4];
#pragma unroll
    for (int mt = 0; mt < 2; mt++)
#pragma unroll
        for (int nt = 0; nt < 4; nt++)
#pragma unroll
            for (int q = 0; q < 4; q++) acc[mt][nt][q] = 0.f;

    auto load_stage = [&](int s, int ktile) {
        const size_t ko = (size_t)ktile * BKF;
        {
            int r = tid >> 2, cc = tid & 3;
            uint32_t so = (uint32_t)(((s * TMF + r) * STR + cc * 8) * 2);
            size_t go = (size_t)r * lda + ko + cc * 8;
            cp16(ah_sm + so, AgH + go);
            cp16(al_sm + so, AgL + go);
        }
#pragma unroll
        for (int l = 0; l < 2; l++) {
            int v = tid + l * 256;
            int r = v >> 2, cc = v & 3;
            uint32_t so = (uint32_t)(((s * TNF + r) * STR + cc * 8) * 2);
            size_t go = (size_t)r * ldb + ko + cc * 8;
            cp16(bh_sm + so, BgH + go);
            cp16(bl_sm + so, BgL + go);
        }
    };

    const int NKT = K / BKF;
    load_stage(0, 0); CP_COMMIT();

    for (int kt = 0; kt < NKT; kt++) {
        __syncthreads();
        if (kt + 1 < NKT) {
            load_stage((kt + 1) & 1, kt + 1);
            CP_COMMIT();
            CP_WAIT1();
        } else {
            CP_WAIT0();
        }
        __syncthreads();

        const __nv_bfloat16* AbH = AH + (kt & 1) * A_ST;
        const __nv_bfloat16* AbL = AL + (kt & 1) * A_ST;
        const __nv_bfloat16* BbH = BH + (kt & 1) * B_ST;
        const __nv_bfloat16* BbL = BL + (kt & 1) * B_ST;
#pragma unroll
        for (int ks = 0; ks < 2; ks++) {
            const int k0 = ks * 16;
            uint32_t ah[2][4], al[2][4], bh[4][2], bl[4][2];
#pragma unroll
            for (int mt = 0; mt < 2; mt++) {
                const int rb = (wm0 + mt * 16 + gq) * STR + k0 + 2 * tq;
                ah[mt][0] = lds32(AbH + rb);
                ah[mt][1] = lds32(AbH + rb + 8 * STR);
                ah[mt][2] = lds32(AbH + rb + 8);
                ah[mt][3] = lds32(AbH + rb + 8 * STR + 8);
                al[mt][0] = lds32(AbL + rb);
                al[mt][1] = lds32(AbL + rb + 8 * STR);
                al[mt][2] = lds32(AbL + rb + 8);
                al[mt][3] = lds32(AbL + rb + 8 * STR + 8);
            }
#pragma unroll
            for (int nt = 0; nt < 4; nt++) {
                const int rb = (wn0 + nt * 8 + gq) * STR + k0 + 2 * tq;
                bh[nt][0] = lds32(BbH + rb);
                bh[nt][1] = lds32(BbH + rb + 8);
                bl[nt][0] = lds32(BbL + rb);
                bl[nt][1] = lds32(BbL + rb + 8);
            }
#pragma unroll
            for (int mt = 0; mt < 2; mt++)
#pragma unroll
                for (int nt = 0; nt < 4; nt++) {
                    mma_bf16(acc[mt][nt], al[mt], bh[nt]);
                    mma_bf16(acc[mt][nt], ah[mt], bl[nt]);
                    mma_bf16(acc[mt][nt], ah[mt], bh[nt]);
                }
        }
    }

#pragma unroll
    for (int mt = 0; mt < 2; mt++) {
        const int r0 = row0 + wm0 + mt * 16 + gq;
#pragma unroll
        for (int nt = 0; nt < 4; nt++) {
            const int col = col0 + wn0 + nt * 8 + 2 * tq;
            size_t i0 = (size_t)r0 * ldc + col;
            size_t i1 = i0 + (size_t)8 * ldc;
            *(float2*)(Cb + i0) = make_float2(acc[mt][nt][0], acc[mt][nt][1]);
            *(float2*)(Cb + i1) = make_float2(acc[mt][nt][2], acc[mt][nt][3]);
        }
    }
}

// ---------------- elementwise helpers ----------------
__global__ void zero_init_k(float* __restrict__ z,
                            __nv_bfloat16* __restrict__ sh,
                            __nv_bfloat16* __restrict__ sl, int n) {
    int i = blockIdx.x * blockDim.x + threadIdx.x;
    if (i < n) { z[i] = 0.f; sh[i] = __float2bfloat16_rn(0.f); sl[i] = __float2bfloat16_rn(0.f); }
}

__global__ void split_k(const float* __restrict__ in,
                        __nv_bfloat16* __restrict__ h,
                        __nv_bfloat16* __restrict__ l, size_t n) {
    size_t i = (size_t)blockIdx.x * blockDim.x + threadIdx.x;
    if (i >= n) return;
    float v = in[i];
    __nv_bfloat16 hi = __float2bfloat16_rn(v);
    h[i] = hi;
    l[i] = __float2bfloat16_rn(v - __bfloat162float(hi));
}

// G (fp32) -> M2 = TAU*G - I as separate bf16 hi/lo planes.
__global__ void make_M2_k(const float* __restrict__ g,
                          __nv_bfloat16* __restrict__ m2h,
                          __nv_bfloat16* __restrict__ m2l) {
    size_t i = (size_t)blockIdx.x * blockDim.x + threadIdx.x;
    if (i >= (size_t)C_ * D_ * D_) return;
    int d = (int)(i % D_);
    int e = (int)((i / D_) % D_);
    float m = TAU * g[i] - ((e == d) ? 1.f : 0.f);
    __nv_bfloat16 hi = __float2bfloat16_rn(m);
    m2h[i] = hi;
    m2l[i] = __float2bfloat16_rn(m - __bfloat162float(hi));
}

__global__ void scale_y_k(float* __restrict__ y, int n) {
    int i = blockIdx.x * blockDim.x + threadIdx.x;
    if (i < n) y[i] *= TAU;
}

// ---------------- FFMA decoder GEMM (exact fp32 output) ----------------
__global__ __launch_bounds__(256, 2) void gemm_nn_dec_k(
    const float* __restrict__ Z, const float* __restrict__ W,
    float* __restrict__ Out)
{
    const int BM = 128, BN = 128, BK = 16, K = D_;
    __shared__ float As[BK][BM];
    __shared__ float Bs[BK][BN];

    const int c = blockIdx.z;
    const float* A  = Z + c * D_;
    const float* Bp = W + (size_t)c * D_ * N_;
    float* Cp = Out + c * N_;
    const int row0 = blockIdx.y * BM;
    const int col0 = blockIdx.x * BN;
    const int tid = threadIdx.x;
    const int tx = tid & 15;
    const int ty = tid >> 4;

    float acc[8][8];
#pragma unroll
    for (int i = 0; i < 8; i++)
#pragma unroll
        for (int j = 0; j < 8; j++) acc[i][j] = 0.f;

    for (int kt = 0; kt < K; kt += BK) {
#pragma unroll
        for (int l = 0; l < 2; l++) {
            int v = tid + l * 256;
            int m = v >> 2;
            int kq = (v & 3) << 2;
            float4 f = *(const float4*)(A + (size_t)(row0 + m) * CD + kt + kq);
            As[kq + 0][m] = f.x; As[kq + 1][m] = f.y;
            As[kq + 2][m] = f.z; As[kq + 3][m] = f.w;
        }
#pragma unroll
        for (int l = 0; l < 2; l++) {
            int v = tid + l * 256;
            int kr = v >> 5;
            int nq = (v & 31) << 2;
            float4 f = *(const float4*)(Bp + (size_t)(kt + kr) * N_ + col0 + nq);
            *(float4*)&Bs[kr][nq] = f;
        }
        __syncthreads();

#pragma unroll
        for (int k = 0; k < BK; k++) {
            float a[8], b[8];
            *(float4*)&a[0] = *(const float4*)&As[k][ty * 8];
            *(float4*)&a[4] = *(const float4*)&As[k][ty * 8 + 4];
            *(float4*)&b[0] = *(const float4*)&Bs[k][tx * 8];
            *(float4*)&b[4] = *(const float4*)&Bs[k][tx * 8 + 4];
#pragma unroll
            for (int i = 0; i < 8; i++)
#pragma unroll
                for (int j = 0; j < 8; j++)
                    acc[i][j] = fmaf(a[i], b[j], acc[i][j]);
        }
        __syncthreads();
    }

#pragma unroll
    for (int i = 0; i < 8; i++) {
        size_t base = (size_t)(row0 + ty * 8 + i) * CN + col0 + tx * 8;
        *(float4*)&Cp[base]     = make_float4(acc[i][0], acc[i][1], acc[i][2], acc[i][3]);
        *(float4*)&Cp[base + 4] = make_float4(acc[i][4], acc[i][5], acc[i][6], acc[i][7]);
    }
}

extern "C" void kernel_launch(void* const* d_in, const int* in_sizes, int n_in,
                              void* d_out, int out_size)
{
    const float* x = (const float*)d_in[0];
    const float* W = (const float*)d_in[1];
    if (in_sizes[0] != B_ * C_ * N_) { const float* t = x; x = W; W = t; }
    float* out = (float*)d_out;

    float *pg, *py, *pn0, *pn1;
    __nv_bfloat16 *pm2h, *pm2l, *psh0, *psh1, *psl0, *psl1, *pwh, *pwl, *pxh, *pxl;
    cudaGetSymbolAddress((void**)&pg,   g_gram);
    cudaGetSymbolAddress((void**)&pm2h, g_m2h);
    cudaGetSymbolAddress((void**)&pm2l, g_m2l);
    cudaGetSymbolAddress((void**)&py,   g_y);
    cudaGetSymbolAddress((void**)&pn0,  g_n0);
    cudaGetSymbolAddress((void**)&pn1,  g_n1);
    cudaGetSymbolAddress((void**)&psh0, g_sh0);
    cudaGetSymbolAddress((void**)&psh1, g_sh1);
    cudaGetSymbolAddress((void**)&psl0, g_sl0);
    cudaGetSymbolAddress((void**)&psl1, g_sl1);
    cudaGetSymbolAddress((void**)&pwh,  g_wh);
    cudaGetSymbolAddress((void**)&pwl,  g_wl);
    cudaGetSymbolAddress((void**)&pxh,  g_xh);
    cudaGetSymbolAddress((void**)&pxl,  g_xl);

    static int smem_set = 0;
    if (!smem_set) {
        cudaFuncSetAttribute(fista_mma_k, cudaFuncAttributeMaxDynamicSharedMemorySize,
                             SMEM_FISTA);
        cudaFuncSetAttribute(gemm3_nt_k, cudaFuncAttributeMaxDynamicSharedMemorySize,
                             SMEM_FISTA);
        smem_set = 1;
    }

    const int nstate = B_ * C_ * D_;
    zero_init_k<<<(nstate + 255) / 256, 256>>>(pn0, psh0, psl0, nstate);

    // Split W and x into bf16 hi/lo planes
    {
        size_t nw = (size_t)C_ * D_ * N_;
        split_k<<<(unsigned)((nw + 255) / 256), 256>>>(W, pwh, pwl, nw);
        size_t nx = (size_t)B_ * C_ * N_;
        split_k<<<(unsigned)((nx + 255) / 256), 256>>>(x, pxh, pxl, nx);
    }

    // Gram[c] = W_c W_c^T via 3xbf16 MMA (error ~1e-7 abs, below M2 quantization)
    gemm3_nt_k<<<dim3(D_ / TNF, D_ / TMF, C_), 256, SMEM_FISTA>>>(
        pwh, pwl, N_, (size_t)D_ * N_,
        pwh, pwl, N_, (size_t)D_ * N_,
        pg, D_, (size_t)D_ * D_, N_);

    // y[b,c,d] = sum_n x[b,c,n] W[c,d,n] via 3xbf16 MMA
    gemm3_nt_k<<<dim3(D_ / TNF, B_ / TMF, C_), 256, SMEM_FISTA>>>(
        pxh, pxl, CN, (size_t)N_,
        pwh, pwl, N_, (size_t)D_ * N_,
        py, CD, (size_t)D_, N_);

    // M2 = TAU*G - I -> bf16 hi/lo planes; y2 = TAU*y
    {
        size_t ng = (size_t)C_ * D_ * D_;
        make_M2_k<<<(unsigned)((ng + 255) / 256), 256>>>(pg, pm2h, pm2l);
        scale_y_k<<<(nstate + 255) / 256, 256>>>(py, nstate);
    }

    // 30 FISTA iterations: 3xBF16 split-precision tensor-core GEMM, one wave/iter
    float t = 1.f;
    __nv_bfloat16 *shi = psh0, *sli = psl0, *sho = psh1, *slo = psl1;
    float *no = pn0, *nn = pn1;
    for (int it = 0; it < NLAYERS; it++) {
        float tnv = (1.f + sqrtf(1.f + 4.f * t * t)) * 0.5f;
        float mu = (t - 1.f) / tnv;
        fista_mma_k<<<dim3(D_ / TNF, B_ / TMF, C_), 256, SMEM_FISTA>>>(
            shi, sli, no, nn, sho, slo, pm2h, pm2l, py, mu);
        __nv_bfloat16* tb;
        tb = shi; shi = sho; sho = tb;
        tb = sli; sli = slo; slo = tb;
        float* t1 = no; no = nn; nn = t1;
        t = tnv;
    }

    // decoder: out = z @ W (exact fp32); final z in `no` after last swap
    gemm_nn_dec_k<<<dim3(8, 4, 3), 256>>>(no, W, out);
}

// round 16
// speedup vs baseline: 2.1538x; 1.0650x over previous
#include <cuda_runtime.h>
#include <cuda_bf16.h>
#include <math.h>
#include <stdint.h>

#define B_ 512
#define C_ 3
#define N_ 1024
#define D_ 2048
#define CD (C_*D_)
#define CN (C_*N_)
#define TAU 0.1f
#define LAM 0.1f
#define NLAYERS 30

// ---------------- scratch (static device globals) ----------------
__device__ float          g_gram[(size_t)C_ * D_ * D_];  // fp32 Gram temp
__device__ __nv_bfloat16  g_m2h[(size_t)C_ * D_ * D_];   // hi bf16 of M2 = TAU*G - I
__device__ __nv_bfloat16  g_m2l[(size_t)C_ * D_ * D_];   // lo bf16 of M2
__device__ float          g_y[(size_t)B_ * C_ * D_];     // y2 = TAU * y
__device__ float          g_n0[(size_t)B_ * C_ * D_];    // z state fp32, ping
__device__ float          g_n1[(size_t)B_ * C_ * D_];    // pong
__device__ __nv_bfloat16  g_sh0[(size_t)B_ * C_ * D_];   // momentum hi, ping
__device__ __nv_bfloat16  g_sh1[(size_t)B_ * C_ * D_];   // pong
__device__ __nv_bfloat16  g_sl0[(size_t)B_ * C_ * D_];   // momentum lo, ping
__device__ __nv_bfloat16  g_sl1[(size_t)B_ * C_ * D_];   // pong
__device__ __nv_bfloat16  g_wh[(size_t)C_ * D_ * N_];    // W split hi (d-major)
__device__ __nv_bfloat16  g_wl[(size_t)C_ * D_ * N_];    // W split lo
__device__ __nv_bfloat16  g_xh[(size_t)B_ * C_ * N_];    // x split hi
__device__ __nv_bfloat16  g_xl[(size_t)B_ * C_ * N_];    // x split lo
__device__ __nv_bfloat16  g_wth[(size_t)C_ * N_ * D_];   // W^T split hi (n-major)
__device__ __nv_bfloat16  g_wtl[(size_t)C_ * N_ * D_];   // W^T split lo
__device__ __nv_bfloat16  g_zh[(size_t)B_ * C_ * D_];    // final z split hi
__device__ __nv_bfloat16  g_zl[(size_t)B_ * C_ * D_];    // final z split lo

// ---------------- helpers ----------------
__device__ __forceinline__ uint32_t smem_u32(const void* p) {
    uint32_t a;
    asm("{ .reg .u64 t; cvta.to.shared.u64 t, %1; cvt.u32.u64 %0, t; }" : "=r"(a) : "l"(p));
    return a;
}
__device__ __forceinline__ void cp16(uint32_t dst, const void* src) {
    asm volatile("cp.async.cg.shared.global [%0], [%1], 16;" :: "r"(dst), "l"(src));
}
#define CP_COMMIT() asm volatile("cp.async.commit_group;" ::: "memory")
#define CP_WAIT1()  asm volatile("cp.async.wait_group 1;" ::: "memory")
#define CP_WAIT0()  asm volatile("cp.async.wait_group 0;" ::: "memory")

__device__ __forceinline__ void mma_bf16(float* c, const uint32_t* a, const uint32_t* b) {
    asm volatile(
        "mma.sync.aligned.m16n8k16.row.col.f32.bf16.bf16.f32 "
        "{%0,%1,%2,%3}, {%4,%5,%6,%7}, {%8,%9}, {%0,%1,%2,%3};"
        : "+f"(c[0]), "+f"(c[1]), "+f"(c[2]), "+f"(c[3])
        : "r"(a[0]), "r"(a[1]), "r"(a[2]), "r"(a[3]), "r"(b[0]), "r"(b[1]));
}
__device__ __forceinline__ void ldsm4(uint32_t* r, uint32_t addr) {
    asm volatile("ldmatrix.sync.aligned.m8n8.x4.shared.b16 {%0,%1,%2,%3}, [%4];"
                 : "=r"(r[0]), "=r"(r[1]), "=r"(r[2]), "=r"(r[3]) : "r"(addr));
}

// ---------------- shared tile config ----------------
#define TMF 64
#define TNF 128
#define BKF 32
#define STR 40                         // bf16 per smem row (80B; banks conflict-free)
#define A_ST (TMF*STR)                 // 2560 bf16 per stage
#define B_ST (TNF*STR)                 // 5120 bf16 per stage
#define SMEM_FISTA ((4*A_ST + 4*B_ST) * 2)  // 61440 B

// ldmatrix per-lane source offsets (in bf16 units, within a tile):
//  A x4: m0 rows0-7 k0-7, m1 rows8-15 k0-7, m2 rows0-7 k8-15, m3 rows8-15 k8-15
//  B x4: m0 ntA k0-7,     m1 ntA k8-15,     m2 ntB k0-7,      m3 ntB k8-15
#define A_LANE_OFF(wm0, lane) (((wm0) + ((lane) & 15)) * STR + ((((lane) >> 4) & 1) << 3))
#define B_LANE_OFF(wn0, lane) (((wn0) + ((lane) & 7) + ((((lane) >> 4) & 1) << 3)) * STR \
                               + ((((lane) >> 3) & 1) << 3))

// ============================================================================
// fista 3xBF16 mma kernel (ldmatrix fragment loads)
// ============================================================================
__global__ __launch_bounds__(256, 3) void fista_mma_k(
    const __nv_bfloat16* __restrict__ sh_in, const __nv_bfloat16* __restrict__ sl_in,
    const float* __restrict__ xo_in,
    float* __restrict__ xn_out,
    __nv_bfloat16* __restrict__ sh_out, __nv_bfloat16* __restrict__ sl_out,
    const __nv_bfloat16* __restrict__ M2h, const __nv_bfloat16* __restrict__ M2l,
    const float* __restrict__ y2, float mu)
{
    extern __shared__ __nv_bfloat16 smem[];
    __nv_bfloat16* AH = smem;
    __nv_bfloat16* AL = smem + 2 * A_ST;
    __nv_bfloat16* BH = smem + 4 * A_ST;
    __nv_bfloat16* BL = smem + 4 * A_ST + 2 * B_ST;

    const int tid = threadIdx.x;
    const int wid = tid >> 5, lane = tid & 31;
    const int c = blockIdx.z;
    const int row0 = blockIdx.y * TMF, col0 = blockIdx.x * TNF;
    const int wm0 = (wid >> 2) * 32;
    const int wn0 = (wid & 3) * 32;
    const int gq = lane >> 2, tq = lane & 3;

    const __nv_bfloat16* AgH = sh_in + (size_t)row0 * CD + (size_t)c * D_;
    const __nv_bfloat16* AgL = sl_in + (size_t)row0 * CD + (size_t)c * D_;
    const __nv_bfloat16* BgH = M2h + (size_t)c * D_ * D_ + (size_t)col0 * D_;
    const __nv_bfloat16* BgL = M2l + (size_t)c * D_ * D_ + (size_t)col0 * D_;

    const uint32_t ah_sm = smem_u32(AH);
    const uint32_t al_sm = smem_u32(AL);
    const uint32_t bh_sm = smem_u32(BH);
    const uint32_t bl_sm = smem_u32(BL);

    const uint32_t a_off = (uint32_t)A_LANE_OFF(wm0, lane);
    const uint32_t b_off = (uint32_t)B_LANE_OFF(wn0, lane);

    float acc[2][4][4];
#pragma unroll
    for (int mt = 0; mt < 2; mt++)
#pragma unroll
        for (int nt = 0; nt < 4; nt++)
#pragma unroll
            for (int q = 0; q < 4; q++) acc[mt][nt][q] = 0.f;

    auto load_stage = [&](int s, int ktile) {
        const size_t ko = (size_t)ktile * BKF;
        {
            int r = tid >> 2, cc = tid & 3;
            uint32_t so = (uint32_t)(((s * TMF + r) * STR + cc * 8) * 2);
            size_t go = (size_t)r * CD + ko + cc * 8;
            cp16(ah_sm + so, AgH + go);
            cp16(al_sm + so, AgL + go);
        }
#pragma unroll
        for (int l = 0; l < 2; l++) {
            int v = tid + l * 256;
            int r = v >> 2, cc = v & 3;
            uint32_t so = (uint32_t)(((s * TNF + r) * STR + cc * 8) * 2);
            size_t go = (size_t)r * D_ + ko + cc * 8;
            cp16(bh_sm + so, BgH + go);
            cp16(bl_sm + so, BgL + go);
        }
    };

    const int NKT = D_ / BKF;  // 64
    load_stage(0, 0); CP_COMMIT();

    for (int kt = 0; kt < NKT; kt++) {
        __syncthreads();
        if (kt + 1 < NKT) {
            load_stage((kt + 1) & 1, kt + 1);
            CP_COMMIT();
            CP_WAIT1();
        } else {
            CP_WAIT0();
        }
        __syncthreads();

        const uint32_t sa = (uint32_t)((kt & 1) * A_ST * 2);
        const uint32_t sb = (uint32_t)((kt & 1) * B_ST * 2);
#pragma unroll
        for (int ks = 0; ks < 2; ks++) {
            const int k0 = ks * 16;
            uint32_t ah[2][4], al[2][4], bh[4][2], bl[4][2];
#pragma unroll
            for (int mt = 0; mt < 2; mt++) {
                uint32_t off = sa + (a_off + mt * 16 * STR + k0) * 2;
                ldsm4(ah[mt], ah_sm + off);
                ldsm4(al[mt], al_sm + off);
            }
#pragma unroll
            for (int p = 0; p < 2; p++) {
                uint32_t off = sb + (b_off + p * 16 * STR + k0) * 2;
                uint32_t t4[4];
                ldsm4(t4, bh_sm + off);
                bh[2*p][0] = t4[0]; bh[2*p][1] = t4[1];
                bh[2*p+1][0] = t4[2]; bh[2*p+1][1] = t4[3];
                ldsm4(t4, bl_sm + off);
                bl[2*p][0] = t4[0]; bl[2*p][1] = t4[1];
                bl[2*p+1][0] = t4[2]; bl[2*p+1][1] = t4[3];
            }
#pragma unroll
            for (int mt = 0; mt < 2; mt++)
#pragma unroll
                for (int nt = 0; nt < 4; nt++) {
                    mma_bf16(acc[mt][nt], al[mt], bh[nt]);
                    mma_bf16(acc[mt][nt], ah[mt], bl[nt]);
                    mma_bf16(acc[mt][nt], ah[mt], bh[nt]);
                }
        }
    }

    // ---- fused epilogue: v = y2 - acc ----
    const size_t cb = (size_t)c * D_;
#pragma unroll
    for (int mt = 0; mt < 2; mt++) {
        const int r0 = row0 + wm0 + mt * 16 + gq;
#pragma unroll
        for (int nt = 0; nt < 4; nt++) {
            const int col = col0 + wn0 + nt * 8 + 2 * tq;
            const size_t i0 = (size_t)r0 * CD + cb + col;
            const size_t i1 = i0 + (size_t)8 * CD;

            float2 y0 = *(const float2*)(y2 + i0);
            float2 y1 = *(const float2*)(y2 + i1);
            float v00 = y0.x - acc[mt][nt][0];
            float v01 = y0.y - acc[mt][nt][1];
            float v10 = y1.x - acc[mt][nt][2];
            float v11 = y1.y - acc[mt][nt][3];

            float ss0 = fmaf(v00, v00, v01 * v01);
            float ss1 = fmaf(v10, v10, v11 * v11);
            ss0 += __shfl_xor_sync(0xffffffffu, ss0, 1);
            ss0 += __shfl_xor_sync(0xffffffffu, ss0, 2);
            ss1 += __shfl_xor_sync(0xffffffffu, ss1, 1);
            ss1 += __shfl_xor_sync(0xffffffffu, ss1, 2);
            float sc0 = fmaxf(1.f - (LAM * TAU) / sqrtf(ss0), 0.f);
            float sc1 = fmaxf(1.f - (LAM * TAU) / sqrtf(ss1), 0.f);

            float2 xo0 = *(const float2*)(xo_in + i0);
            float2 xo1 = *(const float2*)(xo_in + i1);

            float z00 = sc0 * fmaxf(v00, 0.f);
            float z01 = sc0 * fmaxf(v01, 0.f);
            float z10 = sc1 * fmaxf(v10, 0.f);
            float z11 = sc1 * fmaxf(v11, 0.f);

            float m00 = fmaf(mu, z00 - xo0.x, z00);
            float m01 = fmaf(mu, z01 - xo0.y, z01);
            float m10 = fmaf(mu, z10 - xo1.x, z10);
            float m11 = fmaf(mu, z11 - xo1.y, z11);

            __nv_bfloat16 h00 = __float2bfloat16_rn(m00);
            __nv_bfloat16 h01 = __float2bfloat16_rn(m01);
            __nv_bfloat16 h10 = __float2bfloat16_rn(m10);
            __nv_bfloat16 h11 = __float2bfloat16_rn(m11);
            __nv_bfloat162 hv0; hv0.x = h00; hv0.y = h01;
            __nv_bfloat162 hv1; hv1.x = h10; hv1.y = h11;
            __nv_bfloat162 lv0;
            lv0.x = __float2bfloat16_rn(m00 - __bfloat162float(h00));
            lv0.y = __float2bfloat16_rn(m01 - __bfloat162float(h01));
            __nv_bfloat162 lv1;
            lv1.x = __float2bfloat16_rn(m10 - __bfloat162float(h10));
            lv1.y = __float2bfloat16_rn(m11 - __bfloat162float(h11));

            *(float2*)(xn_out + i0) = make_float2(z00, z01);
            *(float2*)(xn_out + i1) = make_float2(z10, z11);
            *(__nv_bfloat162*)(sh_out + i0) = hv0;
            *(__nv_bfloat162*)(sh_out + i1) = hv1;
            *(__nv_bfloat162*)(sl_out + i0) = lv0;
            *(__nv_bfloat162*)(sl_out + i1) = lv1;
        }
    }
}

// ============================================================================
// Generic 3xBF16 split NT GEMM with ldmatrix loads (fp32 out, optional alpha)
// ============================================================================
__global__ __launch_bounds__(256, 3) void gemm3_nt_k(
    const __nv_bfloat16* __restrict__ Ah, const __nv_bfloat16* __restrict__ Al,
    int lda, size_t sA,
    const __nv_bfloat16* __restrict__ Bh, const __nv_bfloat16* __restrict__ Bl,
    int ldb, size_t sB,
    float* __restrict__ Cp, int ldc, size_t sC, int K, float alpha)
{
    extern __shared__ __nv_bfloat16 smem[];
    __nv_bfloat16* AH = smem;
    __nv_bfloat16* AL = smem + 2 * A_ST;
    __nv_bfloat16* BH = smem + 4 * A_ST;
    __nv_bfloat16* BL = smem + 4 * A_ST + 2 * B_ST;

    const int tid = threadIdx.x;
    const int wid = tid >> 5, lane = tid & 31;
    const int row0 = blockIdx.y * TMF, col0 = blockIdx.x * TNF;
    const int wm0 = (wid >> 2) * 32;
    const int wn0 = (wid & 3) * 32;
    const int gq = lane >> 2, tq = lane & 3;

    const __nv_bfloat16* AgH = Ah + (size_t)blockIdx.z * sA + (size_t)row0 * lda;
    const __nv_bfloat16* AgL = Al + (size_t)blockIdx.z * sA + (size_t)row0 * lda;
    const __nv_bfloat16* BgH = Bh + (size_t)blockIdx.z * sB + (size_t)col0 * ldb;
    const __nv_bfloat16* BgL = Bl + (size_t)blockIdx.z * sB + (size_t)col0 * ldb;
    float* Cb = Cp + (size_t)blockIdx.z * sC;

    const uint32_t ah_sm = smem_u32(AH);
    const uint32_t al_sm = smem_u32(AL);
    const uint32_t bh_sm = smem_u32(BH);
    const uint32_t bl_sm = smem_u32(BL);

    const uint32_t a_off = (uint32_t)A_LANE_OFF(wm0, lane);
    const uint32_t b_off = (uint32_t)B_LANE_OFF(wn0, lane);

    float acc[2][4][4];
#pragma unroll
    for (int mt = 0; mt < 2; mt++)
#pragma unroll
        for (int nt = 0; nt < 4; nt++)
#pragma unroll
            for (int q = 0; q < 4; q++) acc[mt][nt][q] = 0.f;

    auto load_stage = [&](int s, int ktile) {
        const size_t ko = (size_t)ktile * BKF;
        {
            int r = tid >> 2, cc = tid & 3;
            uint32_t so = (uint32_t)(((s * TMF + r) * STR + cc * 8) * 2);
            size_t go = (size_t)r * lda + ko + cc * 8;
            cp16(ah_sm + so, AgH + go);
            cp16(al_sm + so, AgL + go);
        }
#pragma unroll
        for (int l = 0; l < 2; l++) {
            int v = tid + l * 256;
            int r = v >> 2, cc = v & 3;
            uint32_t so = (uint32_t)(((s * TNF + r) * STR + cc * 8) * 2);
            size_t go = (size_t)r * ldb + ko + cc * 8;
            cp16(bh_sm + so, BgH + go);
            cp16(bl_sm + so, BgL + go);
        }
    };

    const int NKT = K / BKF;
    load_stage(0, 0); CP_COMMIT();

    for (int kt = 0; kt < NKT; kt++) {
        __syncthreads();
        if (kt + 1 < NKT) {
            load_stage((kt + 1) & 1, kt + 1);
            CP_COMMIT();
            CP_WAIT1();
        } else {
            CP_WAIT0();
        }
        __syncthreads();

        const uint32_t sa = (uint32_t)((kt & 1) * A_ST * 2);
        const uint32_t sb = (uint32_t)((kt & 1) * B_ST * 2);
#pragma unroll
        for (int ks = 0; ks < 2; ks++) {
            const int k0 = ks * 16;
            uint32_t ah[2][4], al[2][4], bh[4][2], bl[4][2];
#pragma unroll
            for (int mt = 0; mt < 2; mt++) {
                uint32_t off = sa + (a_off + mt * 16 * STR + k0) * 2;
                ldsm4(ah[mt], ah_sm + off);
                ldsm4(al[mt], al_sm + off);
            }
#pragma unroll
            for (int p = 0; p < 2; p++) {
                uint32_t off = sb + (b_off + p * 16 * STR + k0) * 2;
                uint32_t t4[4];
                ldsm4(t4, bh_sm + off);
                bh[2*p][0] = t4[0]; bh[2*p][1] = t4[1];
                bh[2*p+1][0] = t4[2]; bh[2*p+1][1] = t4[3];
                ldsm4(t4, bl_sm + off);
                bl[2*p][0] = t4[0]; bl[2*p][1] = t4[1];
                bl[2*p+1][0] = t4[2]; bl[2*p+1][1] = t4[3];
            }
#pragma unroll
            for (int mt = 0; mt < 2; mt++)
#pragma unroll
                for (int nt = 0; nt < 4; nt++) {
                    mma_bf16(acc[mt][nt], al[mt], bh[nt]);
                    mma_bf16(acc[mt][nt], ah[mt], bl[nt]);
                    mma_bf16(acc[mt][nt], ah[mt], bh[nt]);
                }
        }
    }

#pragma unroll
    for (int mt = 0; mt < 2; mt++) {
        const int r0 = row0 + wm0 + mt * 16 + gq;
#pragma unroll
        for (int nt = 0; nt < 4; nt++) {
            const int col = col0 + wn0 + nt * 8 + 2 * tq;
            size_t i0 = (size_t)r0 * ldc + col;
            size_t i1 = i0 + (size_t)8 * ldc;
            *(float2*)(Cb + i0) = make_float2(alpha * acc[mt][nt][0], alpha * acc[mt][nt][1]);
            *(float2*)(Cb + i1) = make_float2(alpha * acc[mt][nt][2], alpha * acc[mt][nt][3]);
        }
    }
}

// ---------------- elementwise helpers ----------------
__global__ void zero_init_k(float* __restrict__ z,
                            __nv_bfloat16* __restrict__ sh,
                            __nv_bfloat16* __restrict__ sl, int n) {
    int i = blockIdx.x * blockDim.x + threadIdx.x;
    if (i < n) { z[i] = 0.f; sh[i] = __float2bfloat16_rn(0.f); sl[i] = __float2bfloat16_rn(0.f); }
}

__global__ void split_k(const float* __restrict__ in,
                        __nv_bfloat16* __restrict__ h,
                        __nv_bfloat16* __restrict__ l, size_t n) {
    size_t i = (size_t)blockIdx.x * blockDim.x + threadIdx.x;
    if (i >= n) return;
    float v = in[i];
    __nv_bfloat16 hi = __float2bfloat16_rn(v);
    h[i] = hi;
    l[i] = __float2bfloat16_rn(v - __bfloat162float(hi));
}

// W[c][d][n] -> Wt[c][n][d] split into bf16 hi/lo (for decoder NT GEMM)
__global__ void trans_split_k(const float* __restrict__ W,
                              __nv_bfloat16* __restrict__ th,
                              __nv_bfloat16* __restrict__ tl) {
    __shared__ float t[32][33];
    const int c = blockIdx.z;
    const int d0 = blockIdx.y * 32, n0 = blockIdx.x * 32;
    const float* Wb = W + (size_t)c * D_ * N_;
    for (int j = threadIdx.y; j < 32; j += 8)
        t[j][threadIdx.x] = Wb[(size_t)(d0 + j) * N_ + n0 + threadIdx.x];
    __syncthreads();
    __nv_bfloat16* thb = th + (size_t)c * N_ * D_;
    __nv_bfloat16* tlb = tl + (size_t)c * N_ * D_;
    for (int j = threadIdx.y; j < 32; j += 8) {
        float v = t[threadIdx.x][j];
        __nv_bfloat16 hi = __float2bfloat16_rn(v);
        size_t o = (size_t)(n0 + j) * D_ + d0 + threadIdx.x;
        thb[o] = hi;
        tlb[o] = __float2bfloat16_rn(v - __bfloat162float(hi));
    }
}

// G (fp32) -> M2 = TAU*G - I as separate bf16 hi/lo planes.
__global__ void make_M2_k(const float* __restrict__ g,
                          __nv_bfloat16* __restrict__ m2h,
                          __nv_bfloat16* __restrict__ m2l) {
    size_t i = (size_t)blockIdx.x * blockDim.x + threadIdx.x;
    if (i >= (size_t)C_ * D_ * D_) return;
    int d = (int)(i % D_);
    int e = (int)((i / D_) % D_);
    float m = TAU * g[i] - ((e == d) ? 1.f : 0.f);
    __nv_bfloat16 hi = __float2bfloat16_rn(m);
    m2h[i] = hi;
    m2l[i] = __float2bfloat16_rn(m - __bfloat162float(hi));
}

extern "C" void kernel_launch(void* const* d_in, const int* in_sizes, int n_in,
                              void* d_out, int out_size)
{
    const float* x = (const float*)d_in[0];
    const float* W = (const float*)d_in[1];
    if (in_sizes[0] != B_ * C_ * N_) { const float* t = x; x = W; W = t; }
    float* out = (float*)d_out;

    float *pg, *py, *pn0, *pn1;
    __nv_bfloat16 *pm2h, *pm2l, *psh0, *psh1, *psl0, *psl1;
    __nv_bfloat16 *pwh, *pwl, *pxh, *pxl, *pwth, *pwtl, *pzh, *pzl;
    cudaGetSymbolAddress((void**)&pg,   g_gram);
    cudaGetSymbolAddress((void**)&pm2h, g_m2h);
    cudaGetSymbolAddress((void**)&pm2l, g_m2l);
    cudaGetSymbolAddress((void**)&py,   g_y);
    cudaGetSymbolAddress((void**)&pn0,  g_n0);
    cudaGetSymbolAddress((void**)&pn1,  g_n1);
    cudaGetSymbolAddress((void**)&psh0, g_sh0);
    cudaGetSymbolAddress((void**)&psh1, g_sh1);
    cudaGetSymbolAddress((void**)&psl0, g_sl0);
    cudaGetSymbolAddress((void**)&psl1, g_sl1);
    cudaGetSymbolAddress((void**)&pwh,  g_wh);
    cudaGetSymbolAddress((void**)&pwl,  g_wl);
    cudaGetSymbolAddress((void**)&pxh,  g_xh);
    cudaGetSymbolAddress((void**)&pxl,  g_xl);
    cudaGetSymbolAddress((void**)&pwth, g_wth);
    cudaGetSymbolAddress((void**)&pwtl, g_wtl);
    cudaGetSymbolAddress((void**)&pzh,  g_zh);
    cudaGetSymbolAddress((void**)&pzl,  g_zl);

    static int smem_set = 0;
    if (!smem_set) {
        cudaFuncSetAttribute(fista_mma_k, cudaFuncAttributeMaxDynamicSharedMemorySize,
                             SMEM_FISTA);
        cudaFuncSetAttribute(gemm3_nt_k, cudaFuncAttributeMaxDynamicSharedMemorySize,
                             SMEM_FISTA);
        smem_set = 1;
    }

    const int nstate = B_ * C_ * D_;
    zero_init_k<<<(nstate + 255) / 256, 256>>>(pn0, psh0, psl0, nstate);

    // Split W, x; transpose-split W for the decoder
    {
        size_t nw = (size_t)C_ * D_ * N_;
        split_k<<<(unsigned)((nw + 255) / 256), 256>>>(W, pwh, pwl, nw);
        size_t nx = (size_t)B_ * C_ * N_;
        split_k<<<(unsigned)((nx + 255) / 256), 256>>>(x, pxh, pxl, nx);
        trans_split_k<<<dim3(N_ / 32, D_ / 32, C_), dim3(32, 8)>>>(W, pwth, pwtl);
    }

    // Gram[c] = W_c W_c^T via 3xbf16 MMA
    gemm3_nt_k<<<dim3(D_ / TNF, D_ / TMF, C_), 256, SMEM_FISTA>>>(
        pwh, pwl, N_, (size_t)D_ * N_,
        pwh, pwl, N_, (size_t)D_ * N_,
        pg, D_, (size_t)D_ * D_, N_, 1.f);

    // y2[b,c,d] = TAU * sum_n x[b,c,n] W[c,d,n]  (alpha folds scale_y)
    gemm3_nt_k<<<dim3(D_ / TNF, B_ / TMF, C_), 256, SMEM_FISTA>>>(
        pxh, pxl, CN, (size_t)N_,
        pwh, pwl, N_, (size_t)D_ * N_,
        py, CD, (size_t)D_, N_, TAU);

    // M2 = TAU*G - I -> bf16 hi/lo planes
    {
        size_t ng = (size_t)C_ * D_ * D_;
        make_M2_k<<<(unsigned)((ng + 255) / 256), 256>>>(pg, pm2h, pm2l);
    }

    // 30 FISTA iterations
    float t = 1.f;
    __nv_bfloat16 *shi = psh0, *sli = psl0, *sho = psh1, *slo = psl1;
    float *no = pn0, *nn = pn1;
    for (int it = 0; it < NLAYERS; it++) {
        float tnv = (1.f + sqrtf(1.f + 4.f * t * t)) * 0.5f;
        float mu = (t - 1.f) / tnv;
        fista_mma_k<<<dim3(D_ / TNF, B_ / TMF, C_), 256, SMEM_FISTA>>>(
            shi, sli, no, nn, sho, slo, pm2h, pm2l, py, mu);
        __nv_bfloat16* tb;
        tb = shi; shi = sho; sho = tb;
        tb = sli; sli = slo; slo = tb;
        float* t1 = no; no = nn; nn = t1;
        t = tnv;
    }

    // decoder: out[b,c,n] = sum_d z[b,c,d] W[c,d,n] via 3xbf16 NT (Wt planes)
    split_k<<<(unsigned)((nstate + 255) / 256), 256>>>(no, pzh, pzl, (size_t)nstate);
    gemm3_nt_k<<<dim3(N_ / TNF, B_ / TMF, C_), 256, SMEM_FISTA>>>(
        pzh, pzl, CD, (size_t)D_,
        pwth, pwtl, D_, (size_t)N_ * D_,
        out, CN, (size_t)N_, D_, 1.f);
}

// round 17
// speedup vs baseline: 2.3942x; 1.1116x over previous
#include <cuda_runtime.h>
#include <cuda_bf16.h>
#include <math.h>
#include <stdint.h>

#define B_ 512
#define C_ 3
#define N_ 1024
#define D_ 2048
#define CD (C_*D_)
#define CN (C_*N_)
#define TAU 0.1f
#define LAM 0.1f
#define NLAYERS 30

// ---------------- scratch (static device globals) ----------------
__device__ __nv_bfloat16  g_m2h[(size_t)C_ * D_ * D_];   // hi bf16 of M2 = TAU*G - I
__device__ __nv_bfloat16  g_m2l[(size_t)C_ * D_ * D_];   // lo bf16 of M2
__device__ float          g_y[(size_t)B_ * C_ * D_];     // y2 = TAU * y
__device__ float          g_n0[(size_t)B_ * C_ * D_];    // z state fp32, ping
__device__ float          g_n1[(size_t)B_ * C_ * D_];    // pong
__device__ __nv_bfloat16  g_sh0[(size_t)B_ * C_ * D_];   // momentum hi, ping
__device__ __nv_bfloat16  g_sh1[(size_t)B_ * C_ * D_];   // pong
__device__ __nv_bfloat16  g_sl0[(size_t)B_ * C_ * D_];   // momentum lo, ping
__device__ __nv_bfloat16  g_sl1[(size_t)B_ * C_ * D_];   // pong
__device__ __nv_bfloat16  g_wh[(size_t)C_ * D_ * N_];    // W split hi (d-major)
__device__ __nv_bfloat16  g_wl[(size_t)C_ * D_ * N_];    // W split lo
__device__ __nv_bfloat16  g_xh[(size_t)B_ * C_ * N_];    // x split hi
__device__ __nv_bfloat16  g_xl[(size_t)B_ * C_ * N_];    // x split lo
__device__ __nv_bfloat16  g_wth[(size_t)C_ * N_ * D_];   // W^T split hi (n-major)
__device__ __nv_bfloat16  g_wtl[(size_t)C_ * N_ * D_];   // W^T split lo

// ---------------- helpers ----------------
__device__ __forceinline__ uint32_t smem_u32(const void* p) {
    uint32_t a;
    asm("{ .reg .u64 t; cvta.to.shared.u64 t, %1; cvt.u32.u64 %0, t; }" : "=r"(a) : "l"(p));
    return a;
}
__device__ __forceinline__ void cp16(uint32_t dst, const void* src) {
    asm volatile("cp.async.cg.shared.global [%0], [%1], 16;" :: "r"(dst), "l"(src));
}
#define CP_COMMIT() asm volatile("cp.async.commit_group;" ::: "memory")
#define CP_WAIT0()  asm volatile("cp.async.wait_group 0;" ::: "memory")

__device__ __forceinline__ void mma_bf16(float* c, const uint32_t* a, const uint32_t* b) {
    asm volatile(
        "mma.sync.aligned.m16n8k16.row.col.f32.bf16.bf16.f32 "
        "{%0,%1,%2,%3}, {%4,%5,%6,%7}, {%8,%9}, {%0,%1,%2,%3};"
        : "+f"(c[0]), "+f"(c[1]), "+f"(c[2]), "+f"(c[3])
        : "r"(a[0]), "r"(a[1]), "r"(a[2]), "r"(a[3]), "r"(b[0]), "r"(b[1]));
}
__device__ __forceinline__ void ldsm4(uint32_t* r, uint32_t addr) {
    asm volatile("ldmatrix.sync.aligned.m8n8.x4.shared.b16 {%0,%1,%2,%3}, [%4];"
                 : "=r"(r[0]), "=r"(r[1]), "=r"(r[2]), "=r"(r[3]) : "r"(addr));
}

// ---------------- shared tile config ----------------
#define TMF 64
#define TNF 128
#define BKF 32
#define STR 40
#define A_ST (TMF*STR)
#define B_ST (TNF*STR)
#define SMEM_FISTA ((4*A_ST + 4*B_ST) * 2)  // 61440 B

#define A_LANE_OFF(wm0, lane) (((wm0) + ((lane) & 15)) * STR + ((((lane) >> 4) & 1) << 3))
#define B_LANE_OFF(wn0, lane) (((wn0) + ((lane) & 7) + ((((lane) >> 4) & 1) << 3)) * STR \
                               + ((((lane) >> 3) & 1) << 3))

// shared mainloop body (single sync per k-tile)
#define GEMM3_MAINLOOP(NKT)                                                     \
    load_stage(0, 0); CP_COMMIT();                                              \
    for (int kt = 0; kt < (NKT); kt++) {                                        \
        CP_WAIT0();                                                             \
        __syncthreads();                                                        \
        if (kt + 1 < (NKT)) { load_stage((kt + 1) & 1, kt + 1); CP_COMMIT(); }  \
        const uint32_t sa = (uint32_t)((kt & 1) * A_ST * 2);                    \
        const uint32_t sb = (uint32_t)((kt & 1) * B_ST * 2);                    \
        _Pragma("unroll")                                                       \
        for (int ks = 0; ks < 2; ks++) {                                        \
            const int k0 = ks * 16;                                             \
            uint32_t ah[2][4], al[2][4], bh[4][2], bl[4][2];                    \
            _Pragma("unroll")                                                   \
            for (int mt = 0; mt < 2; mt++) {                                    \
                uint32_t off = sa + (a_off + mt * 16 * STR + k0) * 2;           \
                ldsm4(ah[mt], ah_sm + off);                                     \
                ldsm4(al[mt], al_sm + off);                                     \
            }                                                                   \
            _Pragma("unroll")                                                   \
            for (int p = 0; p < 2; p++) {                                       \
                uint32_t off = sb + (b_off + p * 16 * STR + k0) * 2;            \
                uint32_t t4[4];                                                 \
                ldsm4(t4, bh_sm + off);                                         \
                bh[2*p][0] = t4[0]; bh[2*p][1] = t4[1];                         \
                bh[2*p+1][0] = t4[2]; bh[2*p+1][1] = t4[3];                     \
                ldsm4(t4, bl_sm + off);                                         \
                bl[2*p][0] = t4[0]; bl[2*p][1] = t4[1];                         \
                bl[2*p+1][0] = t4[2]; bl[2*p+1][1] = t4[3];                     \
            }                                                                   \
            _Pragma("unroll")                                                   \
            for (int mt = 0; mt < 2; mt++)                                      \
                _Pragma("unroll")                                               \
                for (int nt = 0; nt < 4; nt++) {                                \
                    mma_bf16(acc[mt][nt], al[mt], bh[nt]);                      \
                    mma_bf16(acc[mt][nt], ah[mt], bl[nt]);                      \
                    mma_bf16(acc[mt][nt], ah[mt], bh[nt]);                      \
                }                                                               \
        }                                                                       \
    }

// ============================================================================
// fista 3xBF16 mma kernel
// ============================================================================
__global__ __launch_bounds__(256, 3) void fista_mma_k(
    const __nv_bfloat16* __restrict__ sh_in, const __nv_bfloat16* __restrict__ sl_in,
    const float* __restrict__ xo_in,
    float* __restrict__ xn_out,
    __nv_bfloat16* __restrict__ sh_out, __nv_bfloat16* __restrict__ sl_out,
    const __nv_bfloat16* __restrict__ M2h, const __nv_bfloat16* __restrict__ M2l,
    const float* __restrict__ y2, float mu)
{
    extern __shared__ __nv_bfloat16 smem[];
    __nv_bfloat16* AH = smem;
    __nv_bfloat16* AL = smem + 2 * A_ST;
    __nv_bfloat16* BH = smem + 4 * A_ST;
    __nv_bfloat16* BL = smem + 4 * A_ST + 2 * B_ST;

    const int tid = threadIdx.x;
    const int wid = tid >> 5, lane = tid & 31;
    const int c = blockIdx.z;
    const int row0 = blockIdx.y * TMF, col0 = blockIdx.x * TNF;
    const int wm0 = (wid >> 2) * 32;
    const int wn0 = (wid & 3) * 32;
    const int gq = lane >> 2, tq = lane & 3;

    const __nv_bfloat16* AgH = sh_in + (size_t)row0 * CD + (size_t)c * D_;
    const __nv_bfloat16* AgL = sl_in + (size_t)row0 * CD + (size_t)c * D_;
    const __nv_bfloat16* BgH = M2h + (size_t)c * D_ * D_ + (size_t)col0 * D_;
    const __nv_bfloat16* BgL = M2l + (size_t)c * D_ * D_ + (size_t)col0 * D_;

    const uint32_t ah_sm = smem_u32(AH);
    const uint32_t al_sm = smem_u32(AL);
    const uint32_t bh_sm = smem_u32(BH);
    const uint32_t bl_sm = smem_u32(BL);

    const uint32_t a_off = (uint32_t)A_LANE_OFF(wm0, lane);
    const uint32_t b_off = (uint32_t)B_LANE_OFF(wn0, lane);

    float acc[2][4][4];
#pragma unroll
    for (int mt = 0; mt < 2; mt++)
#pragma unroll
        for (int nt = 0; nt < 4; nt++)
#pragma unroll
            for (int q = 0; q < 4; q++) acc[mt][nt][q] = 0.f;

    auto load_stage = [&](int s, int ktile) {
        const size_t ko = (size_t)ktile * BKF;
        {
            int r = tid >> 2, cc = tid & 3;
            uint32_t so = (uint32_t)(((s * TMF + r) * STR + cc * 8) * 2);
            size_t go = (size_t)r * CD + ko + cc * 8;
            cp16(ah_sm + so, AgH + go);
            cp16(al_sm + so, AgL + go);
        }
#pragma unroll
        for (int l = 0; l < 2; l++) {
            int v = tid + l * 256;
            int r = v >> 2, cc = v & 3;
            uint32_t so = (uint32_t)(((s * TNF + r) * STR + cc * 8) * 2);
            size_t go = (size_t)r * D_ + ko + cc * 8;
            cp16(bh_sm + so, BgH + go);
            cp16(bl_sm + so, BgL + go);
        }
    };

    GEMM3_MAINLOOP(D_ / BKF)

    // ---- fused epilogue: v = y2 - acc ----
    const size_t cb = (size_t)c * D_;
#pragma unroll
    for (int mt = 0; mt < 2; mt++) {
        const int r0 = row0 + wm0 + mt * 16 + gq;
#pragma unroll
        for (int nt = 0; nt < 4; nt++) {
            const int col = col0 + wn0 + nt * 8 + 2 * tq;
            const size_t i0 = (size_t)r0 * CD + cb + col;
            const size_t i1 = i0 + (size_t)8 * CD;

            float2 y0 = *(const float2*)(y2 + i0);
            float2 y1 = *(const float2*)(y2 + i1);
            float v00 = y0.x - acc[mt][nt][0];
            float v01 = y0.y - acc[mt][nt][1];
            float v10 = y1.x - acc[mt][nt][2];
            float v11 = y1.y - acc[mt][nt][3];

            float ss0 = fmaf(v00, v00, v01 * v01);
            float ss1 = fmaf(v10, v10, v11 * v11);
            ss0 += __shfl_xor_sync(0xffffffffu, ss0, 1);
            ss0 += __shfl_xor_sync(0xffffffffu, ss0, 2);
            ss1 += __shfl_xor_sync(0xffffffffu, ss1, 1);
            ss1 += __shfl_xor_sync(0xffffffffu, ss1, 2);
            float sc0 = fmaxf(1.f - (LAM * TAU) / sqrtf(ss0), 0.f);
            float sc1 = fmaxf(1.f - (LAM * TAU) / sqrtf(ss1), 0.f);

            float2 xo0 = *(const float2*)(xo_in + i0);
            float2 xo1 = *(const float2*)(xo_in + i1);

            float z00 = sc0 * fmaxf(v00, 0.f);
            float z01 = sc0 * fmaxf(v01, 0.f);
            float z10 = sc1 * fmaxf(v10, 0.f);
            float z11 = sc1 * fmaxf(v11, 0.f);

            float m00 = fmaf(mu, z00 - xo0.x, z00);
            float m01 = fmaf(mu, z01 - xo0.y, z01);
            float m10 = fmaf(mu, z10 - xo1.x, z10);
            float m11 = fmaf(mu, z11 - xo1.y, z11);

            __nv_bfloat16 h00 = __float2bfloat16_rn(m00);
            __nv_bfloat16 h01 = __float2bfloat16_rn(m01);
            __nv_bfloat16 h10 = __float2bfloat16_rn(m10);
            __nv_bfloat16 h11 = __float2bfloat16_rn(m11);
            __nv_bfloat162 hv0; hv0.x = h00; hv0.y = h01;
            __nv_bfloat162 hv1; hv1.x = h10; hv1.y = h11;
            __nv_bfloat162 lv0;
            lv0.x = __float2bfloat16_rn(m00 - __bfloat162float(h00));
            lv0.y = __float2bfloat16_rn(m01 - __bfloat162float(h01));
            __nv_bfloat162 lv1;
            lv1.x = __float2bfloat16_rn(m10 - __bfloat162float(h10));
            lv1.y = __float2bfloat16_rn(m11 - __bfloat162float(h11));

            *(float2*)(xn_out + i0) = make_float2(z00, z01);
            *(float2*)(xn_out + i1) = make_float2(z10, z11);
            *(__nv_bfloat162*)(sh_out + i0) = hv0;
            *(__nv_bfloat162*)(sh_out + i1) = hv1;
            *(__nv_bfloat162*)(sl_out + i0) = lv0;
            *(__nv_bfloat162*)(sl_out + i1) = lv1;
        }
    }
}

// ============================================================================
// Generic 3xBF16 split NT GEMM (fp32 out, alpha)
// ============================================================================
__global__ __launch_bounds__(256, 3) void gemm3_nt_k(
    const __nv_bfloat16* __restrict__ Ah, const __nv_bfloat16* __restrict__ Al,
    int lda, size_t sA,
    const __nv_bfloat16* __restrict__ Bh, const __nv_bfloat16* __restrict__ Bl,
    int ldb, size_t sB,
    float* __restrict__ Cp, int ldc, size_t sC, int K, float alpha)
{
    extern __shared__ __nv_bfloat16 smem[];
    __nv_bfloat16* AH = smem;
    __nv_bfloat16* AL = smem + 2 * A_ST;
    __nv_bfloat16* BH = smem + 4 * A_ST;
    __nv_bfloat16* BL = smem + 4 * A_ST + 2 * B_ST;

    const int tid = threadIdx.x;
    const int wid = tid >> 5, lane = tid & 31;
    const int row0 = blockIdx.y * TMF, col0 = blockIdx.x * TNF;
    const int wm0 = (wid >> 2) * 32;
    const int wn0 = (wid & 3) * 32;
    const int gq = lane >> 2, tq = lane & 3;

    const __nv_bfloat16* AgH = Ah + (size_t)blockIdx.z * sA + (size_t)row0 * lda;
    const __nv_bfloat16* AgL = Al + (size_t)blockIdx.z * sA + (size_t)row0 * lda;
    const __nv_bfloat16* BgH = Bh + (size_t)blockIdx.z * sB + (size_t)col0 * ldb;
    const __nv_bfloat16* BgL = Bl + (size_t)blockIdx.z * sB + (size_t)col0 * ldb;
    float* Cb = Cp + (size_t)blockIdx.z * sC;

    const uint32_t ah_sm = smem_u32(AH);
    const uint32_t al_sm = smem_u32(AL);
    const uint32_t bh_sm = smem_u32(BH);
    const uint32_t bl_sm = smem_u32(BL);

    const uint32_t a_off = (uint32_t)A_LANE_OFF(wm0, lane);
    const uint32_t b_off = (uint32_t)B_LANE_OFF(wn0, lane);

    float acc[2][4][4];
#pragma unroll
    for (int mt = 0; mt < 2; mt++)
#pragma unroll
        for (int nt = 0; nt < 4; nt++)
#pragma unroll
            for (int q = 0; q < 4; q++) acc[mt][nt][q] = 0.f;

    auto load_stage = [&](int s, int ktile) {
        const size_t ko = (size_t)ktile * BKF;
        {
            int r = tid >> 2, cc = tid & 3;
            uint32_t so = (uint32_t)(((s * TMF + r) * STR + cc * 8) * 2);
            size_t go = (size_t)r * lda + ko + cc * 8;
            cp16(ah_sm + so, AgH + go);
            cp16(al_sm + so, AgL + go);
        }
#pragma unroll
        for (int l = 0; l < 2; l++) {
            int v = tid + l * 256;
            int r = v >> 2, cc = v & 3;
            uint32_t so = (uint32_t)(((s * TNF + r) * STR + cc * 8) * 2);
            size_t go = (size_t)r * ldb + ko + cc * 8;
            cp16(bh_sm + so, BgH + go);
            cp16(bl_sm + so, BgL + go);
        }
    };

    GEMM3_MAINLOOP(K / BKF)

#pragma unroll
    for (int mt = 0; mt < 2; mt++) {
        const int r0 = row0 + wm0 + mt * 16 + gq;
#pragma unroll
        for (int nt = 0; nt < 4; nt++) {
            const int col = col0 + wn0 + nt * 8 + 2 * tq;
            size_t i0 = (size_t)r0 * ldc + col;
            size_t i1 = i0 + (size_t)8 * ldc;
            *(float2*)(Cb + i0) = make_float2(alpha * acc[mt][nt][0], alpha * acc[mt][nt][1]);
            *(float2*)(Cb + i1) = make_float2(alpha * acc[mt][nt][2], alpha * acc[mt][nt][3]);
        }
    }
}

// ============================================================================
// Gram (upper-triangle blocks only) with fused M2 = TAU*G - I bf16 hi/lo epilogue
// ============================================================================
__global__ __launch_bounds__(256, 3) void gram3_k(
    const __nv_bfloat16* __restrict__ Wh, const __nv_bfloat16* __restrict__ Wl,
    __nv_bfloat16* __restrict__ m2h, __nv_bfloat16* __restrict__ m2l)
{
    const int row0 = blockIdx.y * TMF, col0 = blockIdx.x * TNF;
    if (col0 + TNF <= row0) return;   // tile strictly below diagonal: mirrored later

    extern __shared__ __nv_bfloat16 smem[];
    __nv_bfloat16* AH = smem;
    __nv_bfloat16* AL = smem + 2 * A_ST;
    __nv_bfloat16* BH = smem + 4 * A_ST;
    __nv_bfloat16* BL = smem + 4 * A_ST + 2 * B_ST;

    const int tid = threadIdx.x;
    const int wid = tid >> 5, lane = tid & 31;
    const int c = blockIdx.z;
    const int wm0 = (wid >> 2) * 32;
    const int wn0 = (wid & 3) * 32;
    const int gq = lane >> 2, tq = lane & 3;

    const __nv_bfloat16* AgH = Wh + (size_t)c * D_ * N_ + (size_t)row0 * N_;
    const __nv_bfloat16* AgL = Wl + (size_t)c * D_ * N_ + (size_t)row0 * N_;
    const __nv_bfloat16* BgH = Wh + (size_t)c * D_ * N_ + (size_t)col0 * N_;
    const __nv_bfloat16* BgL = Wl + (size_t)c * D_ * N_ + (size_t)col0 * N_;

    const uint32_t ah_sm = smem_u32(AH);
    const uint32_t al_sm = smem_u32(AL);
    const uint32_t bh_sm = smem_u32(BH);
    const uint32_t bl_sm = smem_u32(BL);

    const uint32_t a_off = (uint32_t)A_LANE_OFF(wm0, lane);
    const uint32_t b_off = (uint32_t)B_LANE_OFF(wn0, lane);

    float acc[2][4][4];
#pragma unroll
    for (int mt = 0; mt < 2; mt++)
#pragma unroll
        for (int nt = 0; nt < 4; nt++)
#pragma unroll
            for (int q = 0; q < 4; q++) acc[mt][nt][q] = 0.f;

    auto load_stage = [&](int s, int ktile) {
        const size_t ko = (size_t)ktile * BKF;
        {
            int r = tid >> 2, cc = tid & 3;
            uint32_t so = (uint32_t)(((s * TMF + r) * STR + cc * 8) * 2);
            size_t go = (size_t)r * N_ + ko + cc * 8;
            cp16(ah_sm + so, AgH + go);
            cp16(al_sm + so, AgL + go);
        }
#pragma unroll
        for (int l = 0; l < 2; l++) {
            int v = tid + l * 256;
            int r = v >> 2, cc = v & 3;
            uint32_t so = (uint32_t)(((s * TNF + r) * STR + cc * 8) * 2);
            size_t go = (size_t)r * N_ + ko + cc * 8;
            cp16(bh_sm + so, BgH + go);
            cp16(bl_sm + so, BgL + go);
        }
    };

    GEMM3_MAINLOOP(N_ / BKF)

    __nv_bfloat16* Hh = m2h + (size_t)c * D_ * D_;
    __nv_bfloat16* Hl = m2l + (size_t)c * D_ * D_;
#pragma unroll
    for (int mt = 0; mt < 2; mt++) {
        const int r0 = row0 + wm0 + mt * 16 + gq;
#pragma unroll
        for (int nt = 0; nt < 4; nt++) {
            const int col = col0 + wn0 + nt * 8 + 2 * tq;
#pragma unroll
            for (int half = 0; half < 2; half++) {
                const int r = r0 + half * 8;
                float m0 = TAU * acc[mt][nt][2*half]   - ((r == col)     ? 1.f : 0.f);
                float m1 = TAU * acc[mt][nt][2*half+1] - ((r == col + 1) ? 1.f : 0.f);
                __nv_bfloat16 h0 = __float2bfloat16_rn(m0);
                __nv_bfloat16 h1 = __float2bfloat16_rn(m1);
                __nv_bfloat162 hv; hv.x = h0; hv.y = h1;
                __nv_bfloat162 lv;
                lv.x = __float2bfloat16_rn(m0 - __bfloat162float(h0));
                lv.y = __float2bfloat16_rn(m1 - __bfloat162float(h1));
                size_t o = (size_t)r * D_ + col;
                *(__nv_bfloat162*)(Hh + o) = hv;
                *(__nv_bfloat162*)(Hl + o) = lv;
            }
        }
    }
}

// Mirror lower triangle of M2 from the upper (both planes), 32x32 smem transpose.
__global__ void mirror_k(__nv_bfloat16* __restrict__ h, __nv_bfloat16* __restrict__ l) {
    const int ti = blockIdx.y, tj = blockIdx.x;   // dest rows d0=32ti, cols e0=32tj
    if (ti < tj) return;
    __shared__ __nv_bfloat16 th[32][33], tl[32][33];
    const int c = blockIdx.z;
    const int d0 = ti * 32, e0 = tj * 32;
    __nv_bfloat16* H = h + (size_t)c * D_ * D_;
    __nv_bfloat16* L = l + (size_t)c * D_ * D_;
    // source tile: rows e0..e0+32, cols d0..d0+32 (upper triangle)
    for (int j = threadIdx.y; j < 32; j += 8) {
        th[j][threadIdx.x] = H[(size_t)(e0 + j) * D_ + d0 + threadIdx.x];
        tl[j][threadIdx.x] = L[(size_t)(e0 + j) * D_ + d0 + threadIdx.x];
    }
    __syncthreads();
    for (int j = threadIdx.y; j < 32; j += 8) {
        int d = d0 + j, e = e0 + threadIdx.x;
        if (d > e) {
            H[(size_t)d * D_ + e] = th[threadIdx.x][j];
            L[(size_t)d * D_ + e] = tl[threadIdx.x][j];
        }
    }
}

// ---------------- elementwise helpers ----------------
__global__ void zero_init_k(float* __restrict__ z,
                            __nv_bfloat16* __restrict__ sh,
                            __nv_bfloat16* __restrict__ sl, int n) {
    int i = blockIdx.x * blockDim.x + threadIdx.x;
    if (i < n) { z[i] = 0.f; sh[i] = __float2bfloat16_rn(0.f); sl[i] = __float2bfloat16_rn(0.f); }
}

__global__ void split_k(const float* __restrict__ in,
                        __nv_bfloat16* __restrict__ h,
                        __nv_bfloat16* __restrict__ l, size_t n) {
    size_t i = (size_t)blockIdx.x * blockDim.x + threadIdx.x;
    if (i >= n) return;
    float v = in[i];
    __nv_bfloat16 hi = __float2bfloat16_rn(v);
    h[i] = hi;
    l[i] = __float2bfloat16_rn(v - __bfloat162float(hi));
}

// W[c][d][n] -> Wt[c][n][d] split into bf16 hi/lo (for decoder NT GEMM)
__global__ void trans_split_k(const float* __restrict__ W,
                              __nv_bfloat16* __restrict__ th,
                              __nv_bfloat16* __restrict__ tl) {
    __shared__ float t[32][33];
    const int c = blockIdx.z;
    const int d0 = blockIdx.y * 32, n0 = blockIdx.x * 32;
    const float* Wb = W + (size_t)c * D_ * N_;
    for (int j = threadIdx.y; j < 32; j += 8)
        t[j][threadIdx.x] = Wb[(size_t)(d0 + j) * N_ + n0 + threadIdx.x];
    __syncthreads();
    __nv_bfloat16* thb = th + (size_t)c * N_ * D_;
    __nv_bfloat16* tlb = tl + (size_t)c * N_ * D_;
    for (int j = threadIdx.y; j < 32; j += 8) {
        float v = t[threadIdx.x][j];
        __nv_bfloat16 hi = __float2bfloat16_rn(v);
        size_t o = (size_t)(n0 + j) * D_ + d0 + threadIdx.x;
        thb[o] = hi;
        tlb[o] = __float2bfloat16_rn(v - __bfloat162float(hi));
    }
}

extern "C" void kernel_launch(void* const* d_in, const int* in_sizes, int n_in,
                              void* d_out, int out_size)
{
    const float* x = (const float*)d_in[0];
    const float* W = (const float*)d_in[1];
    if (in_sizes[0] != B_ * C_ * N_) { const float* t = x; x = W; W = t; }
    float* out = (float*)d_out;

    float *py, *pn0, *pn1;
    __nv_bfloat16 *pm2h, *pm2l, *psh0, *psh1, *psl0, *psl1;
    __nv_bfloat16 *pwh, *pwl, *pxh, *pxl, *pwth, *pwtl;
    cudaGetSymbolAddress((void**)&pm2h, g_m2h);
    cudaGetSymbolAddress((void**)&pm2l, g_m2l);
    cudaGetSymbolAddress((void**)&py,   g_y);
    cudaGetSymbolAddress((void**)&pn0,  g_n0);
    cudaGetSymbolAddress((void**)&pn1,  g_n1);
    cudaGetSymbolAddress((void**)&psh0, g_sh0);
    cudaGetSymbolAddress((void**)&psh1, g_sh1);
    cudaGetSymbolAddress((void**)&psl0, g_sl0);
    cudaGetSymbolAddress((void**)&psl1, g_sl1);
    cudaGetSymbolAddress((void**)&pwh,  g_wh);
    cudaGetSymbolAddress((void**)&pwl,  g_wl);
    cudaGetSymbolAddress((void**)&pxh,  g_xh);
    cudaGetSymbolAddress((void**)&pxl,  g_xl);
    cudaGetSymbolAddress((void**)&pwth, g_wth);
    cudaGetSymbolAddress((void**)&pwtl, g_wtl);

    static int smem_set = 0;
    if (!smem_set) {
        cudaFuncSetAttribute(fista_mma_k, cudaFuncAttributeMaxDynamicSharedMemorySize,
                             SMEM_FISTA);
        cudaFuncSetAttribute(gemm3_nt_k, cudaFuncAttributeMaxDynamicSharedMemorySize,
                             SMEM_FISTA);
        cudaFuncSetAttribute(gram3_k, cudaFuncAttributeMaxDynamicSharedMemorySize,
                             SMEM_FISTA);
        smem_set = 1;
    }

    const int nstate = B_ * C_ * D_;
    zero_init_k<<<(nstate + 255) / 256, 256>>>(pn0, psh0, psl0, nstate);

    // Split W, x; transpose-split W for the decoder
    {
        size_t nw = (size_t)C_ * D_ * N_;
        split_k<<<(unsigned)((nw + 255) / 256), 256>>>(W, pwh, pwl, nw);
        size_t nx = (size_t)B_ * C_ * N_;
        split_k<<<(unsigned)((nx + 255) / 256), 256>>>(x, pxh, pxl, nx);
        trans_split_k<<<dim3(N_ / 32, D_ / 32, C_), dim3(32, 8)>>>(W, pwth, pwtl);
    }

    // M2 = TAU*(W W^T) - I directly in bf16 hi/lo (upper blocks), then mirror
    gram3_k<<<dim3(D_ / TNF, D_ / TMF, C_), 256, SMEM_FISTA>>>(pwh, pwl, pm2h, pm2l);
    mirror_k<<<dim3(D_ / 32, D_ / 32, C_), dim3(32, 8)>>>(pm2h, pm2l);

    // y2[b,c,d] = TAU * sum_n x[b,c,n] W[c,d,n]
    gemm3_nt_k<<<dim3(D_ / TNF, B_ / TMF, C_), 256, SMEM_FISTA>>>(
        pxh, pxl, CN, (size_t)N_,
        pwh, pwl, N_, (size_t)D_ * N_,
        py, CD, (size_t)D_, N_, TAU);

    // 30 FISTA iterations; last one uses mu=0 so momentum planes == split(z)
    float t = 1.f;
    __nv_bfloat16 *shi = psh0, *sli = psl0, *sho = psh1, *slo = psl1;
    float *no = pn0, *nn = pn1;
    for (int it = 0; it < NLAYERS; it++) {
        float tnv = (1.f + sqrtf(1.f + 4.f * t * t)) * 0.5f;
        float mu = (it == NLAYERS - 1) ? 0.f : (t - 1.f) / tnv;
        fista_mma_k<<<dim3(D_ / TNF, B_ / TMF, C_), 256, SMEM_FISTA>>>(
            shi, sli, no, nn, sho, slo, pm2h, pm2l, py, mu);
        __nv_bfloat16* tb;
        tb = shi; shi = sho; sho = tb;
        tb = sli; sli = slo; slo = tb;
        float* t1 = no; no = nn; nn = t1;
        t = tnv;
    }

    // decoder: out[b,c,n] = sum_d z[b,c,d] W[c,d,n]; z split == (shi, sli)
    gemm3_nt_k<<<dim3(N_ / TNF, B_ / TMF, C_), 256, SMEM_FISTA>>>(
        shi, sli, CD, (size_t)D_,
        pwth, pwtl, D_, (size_t)N_ * D_,
        out, CN, (size_t)N_, D_, 1.f);
}